// round 1
// baseline (speedup 1.0000x reference)
#include <cuda_runtime.h>

#define Bv 4
#define Sv 2048
#define Hv 768
#define NHv 12
#define DHv 64
#define WHv 128

// ---------------- scratch (static device globals; no runtime allocation) ----
__device__ float g_Q [(size_t)Bv*NHv*Sv*DHv];   // [b,nh,s,dh]
__device__ float g_Kt[(size_t)Bv*NHv*DHv*Sv];   // [b,nh,dh,s]  (K transposed)
__device__ float g_V [(size_t)Bv*NHv*Sv*DHv];   // [b,nh,s,dh]
__device__ float g_ctx [(size_t)Bv*Sv*Hv];      // [b,s,H]
__device__ float g_preln[(size_t)Bv*Sv*Hv];     // [b,s,H]
__device__ float g_gates[Bv*NHv*Sv];            // [b,nh,s]
__device__ float g_rowM [Bv*NHv*Sv];
__device__ float g_rowL [Bv*NHv*Sv];

// ---------------- helpers ---------------------------------------------------
__device__ __forceinline__ float blockReduceSum(float v, float* red){
    #pragma unroll
    for (int o=16;o;o>>=1) v += __shfl_xor_sync(0xffffffffu, v, o);
    const int lane = threadIdx.x & 31, wid = threadIdx.x >> 5;
    const int nw = blockDim.x >> 5;
    __syncthreads();
    if (lane==0) red[wid]=v;
    __syncthreads();
    if (threadIdx.x==0){
        float s=0.f;
        for (int i=0;i<nw;i++) s+=red[i];
        red[32]=s;
    }
    __syncthreads();
    return red[32];
}

// ---------------- generic tiled SGEMM with mode-specific epilogues ----------
// MODE 0: C = A@W + bias, stored head-major [b,nh,s,dh]            (Q, V proj)
// MODE 1: C = A@W + bias, stored transposed head-major [b,nh,dh,s] (K proj)
// MODE 2: scores: C = (A@B)*0.125*gate[row] + maskbias[col], row-major batched
// MODE 3: PV: C = A@B, stored to ctx [b,s, nh*64+col]
// MODE 4: C = A@W + bias + resid, row-major                        (Wo proj)
template<int BN, int MODE>
__global__ __launch_bounds__(256) void gemm_kernel(
    const float* __restrict__ Ab, int lda, long long sA,
    const float* __restrict__ Bb, int ldb, long long sB,
    float* __restrict__ Cb, long long sC,
    const float* __restrict__ bias,
    const float* __restrict__ e1,   // gate (MODE2) / resid (MODE4)
    const float* __restrict__ e2,   // attention_mask (MODE2)
    int M, int N, int K)
{
    constexpr int BM=128, BK=8, NW=BN/16;
    const int z = blockIdx.z;
    const float* A  = Ab + (long long)z*sA;
    const float* Bp = Bb + (long long)z*sB;
    const int tid = threadIdx.x;
    const int tx = tid & 15, ty = tid >> 4;
    const int row0 = blockIdx.y*BM, col0 = blockIdx.x*BN;

    __shared__ float As[BK][BM+4];
    __shared__ float Ws[BK][BN];

    float acc[8][NW];
    #pragma unroll
    for (int i=0;i<8;i++)
        #pragma unroll
        for (int j=0;j<NW;j++) acc[i][j]=0.f;

    const int arow = tid>>1,        acol=(tid&1)*4;
    const int brow = tid/(BN/4),    bcol=(tid%(BN/4))*4;
    const float* aptr = A  + (long long)(row0+arow)*lda + acol;
    const float* bptr = Bp + (long long)brow*ldb + col0 + bcol;

    for (int k0=0;k0<K;k0+=BK){
        float4 av = *(const float4*)(aptr + k0);
        As[acol+0][arow]=av.x; As[acol+1][arow]=av.y;
        As[acol+2][arow]=av.z; As[acol+3][arow]=av.w;
        if (brow < BK){
            float4 bv = *(const float4*)(bptr + (long long)k0*ldb);
            *(float4*)&Ws[brow][bcol] = bv;
        }
        __syncthreads();
        #pragma unroll
        for (int k=0;k<BK;k++){
            float a[8], b[NW];
            #pragma unroll
            for (int i=0;i<8;i++) a[i]=As[k][ty*8+i];
            #pragma unroll
            for (int j=0;j<NW;j++) b[j]=Ws[k][tx*NW+j];
            #pragma unroll
            for (int i=0;i<8;i++)
                #pragma unroll
                for (int j=0;j<NW;j++)
                    acc[i][j] = fmaf(a[i], b[j], acc[i][j]);
        }
        __syncthreads();
    }

    #pragma unroll
    for (int i=0;i<8;i++){
        const int row = row0 + ty*8 + i;
        #pragma unroll
        for (int j4=0;j4<NW;j4+=4){
            const int col = col0 + tx*NW + j4;
            float4 v;
            v.x=acc[i][j4]; v.y=acc[i][j4+1]; v.z=acc[i][j4+2]; v.w=acc[i][j4+3];
            if (MODE==0){
                v.x+=bias[col]; v.y+=bias[col+1]; v.z+=bias[col+2]; v.w+=bias[col+3];
                int b=row/Sv, s=row%Sv, nh=col>>6, dh=col&63;
                *(float4*)&Cb[((((long long)b*NHv+nh)*Sv+s)<<6) + dh] = v;
            } else if (MODE==1){
                int b=row/Sv, s=row%Sv;
                float vv[4]={v.x,v.y,v.z,v.w};
                #pragma unroll
                for (int c=0;c<4;c++){
                    int cc=col+c, nh=cc>>6, dh=cc&63;
                    Cb[(((long long)b*NHv+nh)*DHv + dh)*Sv + s] = vv[c] + bias[cc];
                }
            } else if (MODE==2){
                float g = e1[(long long)z*Sv + row]*0.125f;
                const float* mk = e2 + (long long)(z/NHv)*Sv;
                v.x = v.x*g + (1.f-mk[col  ])*-10000.f;
                v.y = v.y*g + (1.f-mk[col+1])*-10000.f;
                v.z = v.z*g + (1.f-mk[col+2])*-10000.f;
                v.w = v.w*g + (1.f-mk[col+3])*-10000.f;
                *(float4*)&Cb[(long long)z*sC + (long long)row*N + col] = v;
            } else if (MODE==3){
                int b=z/NHv, nh=z%NHv;
                *(float4*)&Cb[((long long)b*Sv+row)*Hv + nh*DHv + col] = v;
            } else {
                long long idx = (long long)row*N + col;
                v.x += bias[col  ] + e1[idx  ];
                v.y += bias[col+1] + e1[idx+1];
                v.z += bias[col+2] + e1[idx+2];
                v.w += bias[col+3] + e1[idx+3];
                *(float4*)&Cb[idx] = v;
            }
        }
    }
}

// ---------------- wormhole gate: hs@Wg1+bg1 -> LN -> relu -> @Wg2+bg2 -> sigmoid
__global__ __launch_bounds__(128) void gate_kernel(
    const float* __restrict__ hs, const float* __restrict__ Wg1, const float* __restrict__ bg1,
    const float* __restrict__ glnw, const float* __restrict__ glnb,
    const float* __restrict__ Wg2, const float* __restrict__ bg2,
    float* __restrict__ gates)
{
    const int ROWS=8;
    __shared__ float hs_s[ROWS*Hv];
    __shared__ float g_s[ROWS][WHv+4];
    __shared__ float red[40];
    const int tid = threadIdx.x;
    const long long rowbase = (long long)blockIdx.x*ROWS;

    for (int i=tid;i<ROWS*Hv;i+=128) hs_s[i] = hs[rowbase*Hv + i];
    __syncthreads();

    float acc[ROWS];
    #pragma unroll
    for (int r=0;r<ROWS;r++) acc[r]=bg1[tid];
    for (int h=0;h<Hv;h++){
        float wv = Wg1[h*WHv + tid];
        #pragma unroll
        for (int r=0;r<ROWS;r++) acc[r] = fmaf(hs_s[r*Hv+h], wv, acc[r]);
    }
    float lw = glnw[tid], lb = glnb[tid];
    #pragma unroll
    for (int r=0;r<ROWS;r++){
        float mu  = blockReduceSum(acc[r], red) * (1.f/WHv);
        float d   = acc[r]-mu;
        float var = blockReduceSum(d*d, red) * (1.f/WHv);
        float gv  = d*rsqrtf(var+1e-12f)*lw + lb;
        g_s[r][tid] = fmaxf(gv, 0.f);
    }
    __syncthreads();
    if (tid < ROWS*NHv){
        int r = tid/NHv, o = tid%NHv;
        float s = bg2[o];
        for (int c=0;c<WHv;c++) s = fmaf(g_s[r][c], Wg2[c*NHv+o], s);
        float gate = 1.f/(1.f+__expf(-s));
        long long row = rowbase + r;
        int b = (int)(row/Sv), sq = (int)(row%Sv);
        gates[((long long)b*NHv+o)*Sv + sq] = gate;
    }
}

// ---------------- per-row softmax stats over raw scores ---------------------
__global__ __launch_bounds__(128) void stats_kernel(const float* __restrict__ scores,
    float* __restrict__ rowM, float* __restrict__ rowL)
{
    const long long r = blockIdx.x;
    const float* p = scores + r*(long long)Sv;
    float m=-1e30f, l=0.f;
    for (int i=threadIdx.x;i<Sv;i+=128){
        float v = p[i];
        float nm = fmaxf(m,v);
        l = l*__expf(m-nm) + __expf(v-nm);
        m = nm;
    }
    #pragma unroll
    for (int o=16;o;o>>=1){
        float om = __shfl_xor_sync(0xffffffffu, m, o);
        float ol = __shfl_xor_sync(0xffffffffu, l, o);
        float nm = fmaxf(m, om);
        l = l*__expf(m-nm) + ol*__expf(om-nm);
        m = nm;
    }
    __shared__ float sm[4], sl[4];
    int lane=threadIdx.x&31, wid=threadIdx.x>>5;
    if (lane==0){ sm[wid]=m; sl[wid]=l; }
    __syncthreads();
    if (threadIdx.x==0){
        m=sm[0]; l=sl[0];
        for (int i=1;i<4;i++){
            float nm=fmaxf(m,sm[i]);
            l = l*__expf(m-nm)+sl[i]*__expf(sm[i]-nm);
            m = nm;
        }
        rowM[r]=m; rowL[r]=l;
    }
}

// ---------------- in-place scores -> probs ----------------------------------
__global__ __launch_bounds__(128) void norm_kernel(float* __restrict__ probs,
    const float* __restrict__ rowM, const float* __restrict__ rowL)
{
    const long long r = blockIdx.x;
    float m = rowM[r], inv = 1.f/rowL[r];
    float4* p = (float4*)(probs + r*(long long)Sv);
    for (int i=threadIdx.x;i<Sv/4;i+=128){
        float4 v = p[i];
        v.x=__expf(v.x-m)*inv; v.y=__expf(v.y-m)*inv;
        v.z=__expf(v.z-m)*inv; v.w=__expf(v.w-m)*inv;
        p[i]=v;
    }
}

// ---------------- final residual LayerNorm ----------------------------------
__global__ __launch_bounds__(256) void ln_kernel(const float* __restrict__ x,
    const float* __restrict__ w, const float* __restrict__ b, float* __restrict__ out)
{
    __shared__ float xs[Hv];
    __shared__ float red[40];
    const long long row = blockIdx.x;
    const float* xr = x + row*Hv;
    float partial = 0.f;
    for (int i=threadIdx.x;i<Hv;i+=256){ float v=xr[i]; xs[i]=v; partial+=v; }
    float mu = blockReduceSum(partial, red)*(1.f/Hv);
    float p2=0.f;
    for (int i=threadIdx.x;i<Hv;i+=256){ float d=xs[i]-mu; p2+=d*d; }
    float var = blockReduceSum(p2, red)*(1.f/Hv);
    float rs = rsqrtf(var+1e-12f);
    float* o = out + row*Hv;
    for (int i=threadIdx.x;i<Hv;i+=256) o[i] = (xs[i]-mu)*rs*w[i] + b[i];
}

// ---------------- launcher ---------------------------------------------------
extern "C" void kernel_launch(void* const* d_in, const int* in_sizes, int n_in,
                              void* d_out, int out_size)
{
    const float* hs  =(const float*)d_in[0];
    const float* am  =(const float*)d_in[1];
    const float* Wq  =(const float*)d_in[2];
    const float* bq  =(const float*)d_in[3];
    const float* Wk  =(const float*)d_in[4];
    const float* bk  =(const float*)d_in[5];
    const float* Wv  =(const float*)d_in[6];
    const float* bvb =(const float*)d_in[7];
    const float* Wg1 =(const float*)d_in[8];
    const float* bg1 =(const float*)d_in[9];
    const float* glnw=(const float*)d_in[10];
    const float* glnb=(const float*)d_in[11];
    const float* Wg2 =(const float*)d_in[12];
    const float* bg2 =(const float*)d_in[13];
    const float* Wo  =(const float*)d_in[14];
    const float* bo  =(const float*)d_in[15];
    const float* lnw =(const float*)d_in[16];
    const float* lnb =(const float*)d_in[17];

    float* out   = (float*)d_out;
    float* probs = out + (long long)Bv*Sv*Hv;   // tuple order: (out, probs)

    float *Q,*Kt,*V,*ctx,*preln,*gates,*rowM,*rowL;
    cudaGetSymbolAddress((void**)&Q,     g_Q);
    cudaGetSymbolAddress((void**)&Kt,    g_Kt);
    cudaGetSymbolAddress((void**)&V,     g_V);
    cudaGetSymbolAddress((void**)&ctx,   g_ctx);
    cudaGetSymbolAddress((void**)&preln, g_preln);
    cudaGetSymbolAddress((void**)&gates, g_gates);
    cudaGetSymbolAddress((void**)&rowM,  g_rowM);
    cudaGetSymbolAddress((void**)&rowL,  g_rowL);

    // 1. wormhole gates
    gate_kernel<<<Bv*Sv/8, 128>>>(hs, Wg1, bg1, glnw, glnb, Wg2, bg2, gates);

    // 2. QKV projections (K stored transposed per head)
    dim3 gProj(Hv/128, (Bv*Sv)/128, 1);
    gemm_kernel<128,0><<<gProj,256>>>(hs,Hv,0, Wq,Hv,0, Q ,0, bq ,nullptr,nullptr, Bv*Sv,Hv,Hv);
    gemm_kernel<128,1><<<gProj,256>>>(hs,Hv,0, Wk,Hv,0, Kt,0, bk ,nullptr,nullptr, Bv*Sv,Hv,Hv);
    gemm_kernel<128,0><<<gProj,256>>>(hs,Hv,0, Wv,Hv,0, V ,0, bvb,nullptr,nullptr, Bv*Sv,Hv,Hv);

    // 3. raw scores = (Q K^T)/8 * gate + maskbias  -> written into probs region
    dim3 gScore(Sv/128, Sv/128, Bv*NHv);
    gemm_kernel<128,2><<<gScore,256>>>(Q,DHv,(long long)Sv*DHv, Kt,Sv,(long long)DHv*Sv,
                                       probs,(long long)Sv*Sv, nullptr, gates, am, Sv,Sv,DHv);

    // 4. softmax stats, then in-place normalize to probs
    stats_kernel<<<Bv*NHv*Sv,128>>>(probs, rowM, rowL);
    norm_kernel <<<Bv*NHv*Sv,128>>>(probs, rowM, rowL);

    // 5. ctx = probs @ V   (stored [b,s,H])
    dim3 gPV(1, Sv/128, Bv*NHv);
    gemm_kernel<64,3><<<gPV,256>>>(probs,Sv,(long long)Sv*Sv, V,DHv,(long long)Sv*DHv,
                                   ctx,0, nullptr,nullptr,nullptr, Sv,DHv,Sv);

    // 6. out-projection + bias + residual, then LayerNorm -> out
    gemm_kernel<128,4><<<gProj,256>>>(ctx,Hv,0, Wo,Hv,0, preln,0, bo, hs, nullptr, Bv*Sv,Hv,Hv);
    ln_kernel<<<Bv*Sv,256>>>(preln, lnw, lnb, out);
}

// round 2
// speedup vs baseline: 1.5052x; 1.5052x over previous
#include <cuda_runtime.h>
#include <cuda_bf16.h>

#define Bv 4
#define Sv 2048
#define Hv 768
#define NHv 12
#define DHv 64
#define WHv 128

typedef __nv_bfloat16 bf16;
typedef unsigned int u32;

// ---------------- scratch (static device globals) ---------------------------
__device__ bf16 g_hsh[(size_t)Bv*Sv*Hv];
__device__ bf16 g_hsl[(size_t)Bv*Sv*Hv];
__device__ bf16 g_Wth[(size_t)4*Hv*Hv];     // W^T hi, 4 weights (q,k,v,o)
__device__ bf16 g_Wtl[(size_t)4*Hv*Hv];     // W^T lo
__device__ bf16 g_Qh[(size_t)Bv*NHv*Sv*DHv];
__device__ bf16 g_Ql[(size_t)Bv*NHv*Sv*DHv];
__device__ bf16 g_Kh[(size_t)Bv*NHv*Sv*DHv];
__device__ bf16 g_Kl[(size_t)Bv*NHv*Sv*DHv];
__device__ bf16 g_Vth[(size_t)Bv*NHv*DHv*Sv];   // [z][dh][s]
__device__ bf16 g_Vtl[(size_t)Bv*NHv*DHv*Sv];
__device__ bf16 g_ctxh[(size_t)Bv*Sv*Hv];
__device__ bf16 g_ctxl[(size_t)Bv*Sv*Hv];
__device__ float g_preln[(size_t)Bv*Sv*Hv];
__device__ float g_gates[Bv*NHv*Sv];
__device__ float g_rowM[Bv*NHv*Sv];
__device__ float g_rowL[Bv*NHv*Sv];

// ---------------- mma helper -------------------------------------------------
__device__ __forceinline__ void mma16816(float& c0, float& c1, float& c2, float& c3,
                                         const u32 a[4], const u32 b[2]){
    asm volatile("mma.sync.aligned.m16n8k16.row.col.f32.bf16.bf16.f32 "
        "{%0,%1,%2,%3}, {%4,%5,%6,%7}, {%8,%9}, {%0,%1,%2,%3};"
        : "+f"(c0), "+f"(c1), "+f"(c2), "+f"(c3)
        : "r"(a[0]), "r"(a[1]), "r"(a[2]), "r"(a[3]), "r"(b[0]), "r"(b[1]));
}

// ---------------- split / transpose prep kernels -----------------------------
__global__ __launch_bounds__(256) void split_kernel(const float* __restrict__ x,
    bf16* __restrict__ h, bf16* __restrict__ l, int n4)
{
    int i = blockIdx.x*256 + threadIdx.x;
    if (i >= n4) return;
    float4 v = ((const float4*)x)[i];
    __nv_bfloat162 h01 = __floats2bfloat162_rn(v.x, v.y);
    __nv_bfloat162 h23 = __floats2bfloat162_rn(v.z, v.w);
    __nv_bfloat162 l01 = __floats2bfloat162_rn(v.x-__low2float(h01), v.y-__high2float(h01));
    __nv_bfloat162 l23 = __floats2bfloat162_rn(v.z-__low2float(h23), v.w-__high2float(h23));
    ((__nv_bfloat162*)h)[i*2  ] = h01; ((__nv_bfloat162*)h)[i*2+1] = h23;
    ((__nv_bfloat162*)l)[i*2  ] = l01; ((__nv_bfloat162*)l)[i*2+1] = l23;
}

__global__ __launch_bounds__(256) void wsplit_kernel(
    const float* __restrict__ w0, const float* __restrict__ w1,
    const float* __restrict__ w2, const float* __restrict__ w3)
{
    __shared__ float t[32][33];
    const float* W = blockIdx.z==0 ? w0 : blockIdx.z==1 ? w1 : blockIdx.z==2 ? w2 : w3;
    bf16* oh = g_Wth + (size_t)blockIdx.z*Hv*Hv;
    bf16* ol = g_Wtl + (size_t)blockIdx.z*Hv*Hv;
    int k0 = blockIdx.y*32, n0 = blockIdx.x*32;
    int tx = threadIdx.x & 31, ty = threadIdx.x >> 5;   // (32,8)
    #pragma unroll
    for (int r=0;r<32;r+=8) t[ty+r][tx] = W[(size_t)(k0+ty+r)*Hv + n0+tx];
    __syncthreads();
    #pragma unroll
    for (int r=0;r<32;r+=8){
        float v = t[tx][ty+r];                 // = W[k0+tx][n0+ty+r]
        size_t idx = (size_t)(n0+ty+r)*Hv + k0+tx;
        bf16 h = __float2bfloat16(v);
        oh[idx] = h;
        ol[idx] = __float2bfloat16(v - __bfloat162float(h));
    }
}

// ---------------- generic bf16-split tensor-core GEMM ------------------------
// C[M,N] = A[M,K] @ B^T[N,K]   (3 mma terms: AhBh + AhBl + AlBh)
// MODE 0: Q proj  -> Qh/Ql  [b,nh,s,dh] bf16 pair, +bias
// MODE 1: K proj  -> Kh/Kl  same layout, +bias
// MODE 2: V proj  -> Vth/Vtl [b,nh,dh,s] (transposed), +bias
// MODE 3: scores  -> fp32 raw scores with gate*0.125 + mask bias
// MODE 4: Wo proj -> preln fp32, +bias +resid
template<int MODE>
__global__ __launch_bounds__(256) void mmagemm(
    const bf16* __restrict__ Ah, const bf16* __restrict__ Al, int lda, size_t sA,
    const bf16* __restrict__ Bh, const bf16* __restrict__ Bl, int ldb, size_t sB,
    const float* __restrict__ bias,
    const float* __restrict__ e1,   // gates (MODE3) / resid (MODE4)
    const float* __restrict__ e2,   // attention_mask (MODE3)
    bf16* __restrict__ Oh, bf16* __restrict__ Ol, float* __restrict__ Of,
    int K)
{
    constexpr int LDSK = 40;
    __shared__ bf16 sAh[128*LDSK], sAl[128*LDSK], sBh[128*LDSK], sBl[128*LDSK];
    const int tid  = threadIdx.x, lane = tid & 31, warp = tid >> 5;
    const int grp  = lane >> 2,   tig  = lane & 3;
    const int z    = blockIdx.z;
    const int row0 = blockIdx.y*128, col0 = blockIdx.x*128;
    const bf16* A_h = Ah + (size_t)z*sA;
    const bf16* A_l = Al + (size_t)z*sA;
    const bf16* B_h = Bh + (size_t)z*sB;
    const bf16* B_l = Bl + (size_t)z*sB;
    const int warpM = (warp>>2)*64, warpN = (warp&3)*32;

    float c[4][4][4];
    #pragma unroll
    for (int i=0;i<4;i++)
        #pragma unroll
        for (int j=0;j<4;j++)
            #pragma unroll
            for (int r=0;r<4;r++) c[i][j][r]=0.f;

    const int lr = tid>>2, lcc = (tid&3)*8;

    for (int k0=0;k0<K;k0+=32){
        #pragma unroll
        for (int t=0;t<2;t++){
            int r = lr + t*64;
            *(uint4*)&sAh[r*LDSK+lcc] = *(const uint4*)&A_h[(size_t)(row0+r)*lda + k0+lcc];
            *(uint4*)&sAl[r*LDSK+lcc] = *(const uint4*)&A_l[(size_t)(row0+r)*lda + k0+lcc];
            *(uint4*)&sBh[r*LDSK+lcc] = *(const uint4*)&B_h[(size_t)(col0+r)*ldb + k0+lcc];
            *(uint4*)&sBl[r*LDSK+lcc] = *(const uint4*)&B_l[(size_t)(col0+r)*ldb + k0+lcc];
        }
        __syncthreads();
        #pragma unroll
        for (int ks=0;ks<32;ks+=16){
            u32 a[4][4], bh_[4][2], bl_[4][2];
            #pragma unroll
            for (int j=0;j<4;j++){
                int n = (warpN + j*8 + grp)*LDSK + ks + tig*2;
                bh_[j][0]=*(u32*)&sBh[n]; bh_[j][1]=*(u32*)&sBh[n+8];
                bl_[j][0]=*(u32*)&sBl[n]; bl_[j][1]=*(u32*)&sBl[n+8];
            }
            #pragma unroll
            for (int i=0;i<4;i++){
                int r = (warpM + i*16 + grp)*LDSK + ks + tig*2;
                a[i][0]=*(u32*)&sAh[r];          a[i][1]=*(u32*)&sAh[r+8*LDSK];
                a[i][2]=*(u32*)&sAh[r+8];        a[i][3]=*(u32*)&sAh[r+8*LDSK+8];
            }
            #pragma unroll
            for (int i=0;i<4;i++)
                #pragma unroll
                for (int j=0;j<4;j++){
                    mma16816(c[i][j][0],c[i][j][1],c[i][j][2],c[i][j][3], a[i], bh_[j]);
                    mma16816(c[i][j][0],c[i][j][1],c[i][j][2],c[i][j][3], a[i], bl_[j]);
                }
            #pragma unroll
            for (int i=0;i<4;i++){
                int r = (warpM + i*16 + grp)*LDSK + ks + tig*2;
                a[i][0]=*(u32*)&sAl[r];          a[i][1]=*(u32*)&sAl[r+8*LDSK];
                a[i][2]=*(u32*)&sAl[r+8];        a[i][3]=*(u32*)&sAl[r+8*LDSK+8];
            }
            #pragma unroll
            for (int i=0;i<4;i++)
                #pragma unroll
                for (int j=0;j<4;j++)
                    mma16816(c[i][j][0],c[i][j][1],c[i][j][2],c[i][j][3], a[i], bh_[j]);
        }
        __syncthreads();
    }

    // epilogue: pairs (v0,v1) at (r,cn),(r,cn+1) and (v2,v3) at (r+8,cn..)
    #pragma unroll
    for (int i=0;i<4;i++){
        #pragma unroll
        for (int j=0;j<4;j++){
            int cn = col0 + warpN + j*8 + tig*2;
            #pragma unroll
            for (int half=0; half<2; half++){
                int r = row0 + warpM + i*16 + grp + half*8;
                float v0 = c[i][j][half*2], v1 = c[i][j][half*2+1];
                if (MODE==0 || MODE==1){
                    float x0 = v0 + bias[cn], x1 = v1 + bias[cn+1];
                    int b=r/Sv, s=r-b*Sv, nh=cn>>6, dh=cn&63;
                    size_t idx = (((size_t)(b*NHv+nh)*Sv+s)<<6)+dh;
                    __nv_bfloat162 h = __floats2bfloat162_rn(x0,x1);
                    __nv_bfloat162 l = __floats2bfloat162_rn(x0-__low2float(h), x1-__high2float(h));
                    *(__nv_bfloat162*)(Oh+idx)=h;
                    *(__nv_bfloat162*)(Ol+idx)=l;
                } else if (MODE==2){
                    float x0 = v0 + bias[cn], x1 = v1 + bias[cn+1];
                    int b=r/Sv, s=r-b*Sv, nh=cn>>6, dh=cn&63;
                    size_t i0 = ((size_t)(b*NHv+nh)*DHv+dh)*Sv + s;
                    bf16 h0=__float2bfloat16(x0);
                    Oh[i0]=h0; Ol[i0]=__float2bfloat16(x0-__bfloat162float(h0));
                    bf16 h1=__float2bfloat16(x1);
                    Oh[i0+Sv]=h1; Ol[i0+Sv]=__float2bfloat16(x1-__bfloat162float(h1));
                } else if (MODE==3){
                    float g = e1[(size_t)z*Sv + r]*0.125f;
                    const float* mk = e2 + (size_t)(z/NHv)*Sv;
                    float2 o;
                    o.x = v0*g + (1.f-mk[cn  ])*-10000.f;
                    o.y = v1*g + (1.f-mk[cn+1])*-10000.f;
                    *(float2*)(Of + (size_t)z*Sv*Sv + (size_t)r*Sv + cn) = o;
                } else {
                    size_t idx = (size_t)r*Hv + cn;
                    float2 o;
                    o.x = v0 + bias[cn  ] + e1[idx  ];
                    o.y = v1 + bias[cn+1] + e1[idx+1];
                    *(float2*)(Of+idx) = o;
                }
            }
        }
    }
}

// ---------------- PV: normalize probs in place + ctx = P@V (bf16 split out) --
__global__ __launch_bounds__(256) void pv_kernel(
    float* __restrict__ probs,                 // in: raw scores, out: probs
    const bf16* __restrict__ Vth, const bf16* __restrict__ Vtl,
    const float* __restrict__ rowM, const float* __restrict__ rowL,
    bf16* __restrict__ ctxh, bf16* __restrict__ ctxl)
{
    constexpr int LDSK = 40;
    __shared__ bf16 sPh[128*LDSK], sPl[128*LDSK], sVh[64*LDSK], sVl[64*LDSK];
    __shared__ float sM[128], sI[128];
    const int tid = threadIdx.x, lane = tid & 31, warp = tid >> 5;
    const int grp = lane >> 2, tig = lane & 3;
    const int z = blockIdx.y, q0 = blockIdx.x*128;
    if (tid < 128){
        size_t rr = (size_t)z*Sv + q0 + tid;
        sM[tid] = rowM[rr];
        sI[tid] = 1.f / rowL[rr];
    }
    __syncthreads();
    const int warpM = (warp>>1)*32, warpN = (warp&1)*32;
    float c[2][4][4];
    #pragma unroll
    for (int i=0;i<2;i++)
        #pragma unroll
        for (int j=0;j<4;j++)
            #pragma unroll
            for (int r=0;r<4;r++) c[i][j][r]=0.f;

    float* Pz = probs + (size_t)z*Sv*Sv;
    const bf16* Vh_ = Vth + (size_t)z*DHv*Sv;
    const bf16* Vl_ = Vtl + (size_t)z*DHv*Sv;

    for (int k0=0;k0<Sv;k0+=32){
        #pragma unroll
        for (int t=0;t<4;t++){
            int ch = tid + t*256;
            int r = ch>>3, cc = (ch&7)*4;
            size_t g = (size_t)(q0+r)*Sv + k0 + cc;
            float4 v = *(float4*)&Pz[g];
            float m = sM[r], inv = sI[r];
            float p0=__expf(v.x-m)*inv, p1=__expf(v.y-m)*inv;
            float p2=__expf(v.z-m)*inv, p3=__expf(v.w-m)*inv;
            float4 pv; pv.x=p0; pv.y=p1; pv.z=p2; pv.w=p3;
            *(float4*)&Pz[g] = pv;
            __nv_bfloat162 h01=__floats2bfloat162_rn(p0,p1), h23=__floats2bfloat162_rn(p2,p3);
            __nv_bfloat162 l01=__floats2bfloat162_rn(p0-__low2float(h01), p1-__high2float(h01));
            __nv_bfloat162 l23=__floats2bfloat162_rn(p2-__low2float(h23), p3-__high2float(h23));
            *(__nv_bfloat162*)&sPh[r*LDSK+cc  ]=h01;
            *(__nv_bfloat162*)&sPh[r*LDSK+cc+2]=h23;
            *(__nv_bfloat162*)&sPl[r*LDSK+cc  ]=l01;
            *(__nv_bfloat162*)&sPl[r*LDSK+cc+2]=l23;
        }
        {
            int r = tid>>2, cc = (tid&3)*8;
            size_t g = (size_t)r*Sv + k0 + cc;
            *(uint4*)&sVh[r*LDSK+cc] = *(const uint4*)&Vh_[g];
            *(uint4*)&sVl[r*LDSK+cc] = *(const uint4*)&Vl_[g];
        }
        __syncthreads();
        #pragma unroll
        for (int ks=0;ks<32;ks+=16){
            u32 a[2][4], bh_[4][2], bl_[4][2];
            #pragma unroll
            for (int j=0;j<4;j++){
                int n = (warpN + j*8 + grp)*LDSK + ks + tig*2;
                bh_[j][0]=*(u32*)&sVh[n]; bh_[j][1]=*(u32*)&sVh[n+8];
                bl_[j][0]=*(u32*)&sVl[n]; bl_[j][1]=*(u32*)&sVl[n+8];
            }
            #pragma unroll
            for (int i=0;i<2;i++){
                int r = (warpM + i*16 + grp)*LDSK + ks + tig*2;
                a[i][0]=*(u32*)&sPh[r];       a[i][1]=*(u32*)&sPh[r+8*LDSK];
                a[i][2]=*(u32*)&sPh[r+8];     a[i][3]=*(u32*)&sPh[r+8*LDSK+8];
            }
            #pragma unroll
            for (int i=0;i<2;i++)
                #pragma unroll
                for (int j=0;j<4;j++){
                    mma16816(c[i][j][0],c[i][j][1],c[i][j][2],c[i][j][3], a[i], bh_[j]);
                    mma16816(c[i][j][0],c[i][j][1],c[i][j][2],c[i][j][3], a[i], bl_[j]);
                }
            #pragma unroll
            for (int i=0;i<2;i++){
                int r = (warpM + i*16 + grp)*LDSK + ks + tig*2;
                a[i][0]=*(u32*)&sPl[r];       a[i][1]=*(u32*)&sPl[r+8*LDSK];
                a[i][2]=*(u32*)&sPl[r+8];     a[i][3]=*(u32*)&sPl[r+8*LDSK+8];
            }
            #pragma unroll
            for (int i=0;i<2;i++)
                #pragma unroll
                for (int j=0;j<4;j++)
                    mma16816(c[i][j][0],c[i][j][1],c[i][j][2],c[i][j][3], a[i], bh_[j]);
        }
        __syncthreads();
    }

    const int b = z/NHv, nh = z%NHv;
    #pragma unroll
    for (int i=0;i<2;i++){
        #pragma unroll
        for (int j=0;j<4;j++){
            int dh = warpN + j*8 + tig*2;
            #pragma unroll
            for (int half=0; half<2; half++){
                int s = q0 + warpM + i*16 + grp + half*8;
                float x0 = c[i][j][half*2], x1 = c[i][j][half*2+1];
                size_t idx = ((size_t)b*Sv + s)*Hv + nh*DHv + dh;
                __nv_bfloat162 h = __floats2bfloat162_rn(x0,x1);
                __nv_bfloat162 l = __floats2bfloat162_rn(x0-__low2float(h), x1-__high2float(h));
                *(__nv_bfloat162*)(ctxh+idx)=h;
                *(__nv_bfloat162*)(ctxl+idx)=l;
            }
        }
    }
}

// ---------------- helpers ----------------------------------------------------
__device__ __forceinline__ float blockReduceSum(float v, float* red){
    #pragma unroll
    for (int o=16;o;o>>=1) v += __shfl_xor_sync(0xffffffffu, v, o);
    const int lane = threadIdx.x & 31, wid = threadIdx.x >> 5;
    const int nw = blockDim.x >> 5;
    __syncthreads();
    if (lane==0) red[wid]=v;
    __syncthreads();
    if (threadIdx.x==0){
        float s=0.f;
        for (int i=0;i<nw;i++) s+=red[i];
        red[32]=s;
    }
    __syncthreads();
    return red[32];
}

// ---------------- wormhole gate ----------------------------------------------
__global__ __launch_bounds__(128) void gate_kernel(
    const float* __restrict__ hs, const float* __restrict__ Wg1, const float* __restrict__ bg1,
    const float* __restrict__ glnw, const float* __restrict__ glnb,
    const float* __restrict__ Wg2, const float* __restrict__ bg2,
    float* __restrict__ gates)
{
    const int ROWS=8;
    __shared__ float hs_s[ROWS*Hv];
    __shared__ float g_s[ROWS][WHv+4];
    __shared__ float red[40];
    const int tid = threadIdx.x;
    const size_t rowbase = (size_t)blockIdx.x*ROWS;

    for (int i=tid;i<ROWS*Hv;i+=128) hs_s[i] = hs[rowbase*Hv + i];
    __syncthreads();

    float acc[ROWS];
    #pragma unroll
    for (int r=0;r<ROWS;r++) acc[r]=bg1[tid];
    for (int h=0;h<Hv;h++){
        float wv = Wg1[h*WHv + tid];
        #pragma unroll
        for (int r=0;r<ROWS;r++) acc[r] = fmaf(hs_s[r*Hv+h], wv, acc[r]);
    }
    float lw = glnw[tid], lb = glnb[tid];
    #pragma unroll
    for (int r=0;r<ROWS;r++){
        float mu  = blockReduceSum(acc[r], red) * (1.f/WHv);
        float d   = acc[r]-mu;
        float var = blockReduceSum(d*d, red) * (1.f/WHv);
        float gv  = d*rsqrtf(var+1e-12f)*lw + lb;
        g_s[r][tid] = fmaxf(gv, 0.f);
    }
    __syncthreads();
    if (tid < ROWS*NHv){
        int r = tid/NHv, o = tid%NHv;
        float s = bg2[o];
        for (int c=0;c<WHv;c++) s = fmaf(g_s[r][c], Wg2[c*NHv+o], s);
        float gate = 1.f/(1.f+__expf(-s));
        size_t row = rowbase + r;
        int b = (int)(row/Sv), sq = (int)(row%Sv);
        gates[((size_t)(b*NHv+o))*Sv + sq] = gate;
    }
}

// ---------------- softmax stats ----------------------------------------------
__global__ __launch_bounds__(128) void stats_kernel(const float* __restrict__ scores,
    float* __restrict__ rowM, float* __restrict__ rowL)
{
    const size_t r = blockIdx.x;
    const float* p = scores + r*(size_t)Sv;
    float m=-1e30f, l=0.f;
    for (int i=threadIdx.x;i<Sv;i+=128){
        float v = p[i];
        float nm = fmaxf(m,v);
        l = l*__expf(m-nm) + __expf(v-nm);
        m = nm;
    }
    #pragma unroll
    for (int o=16;o;o>>=1){
        float om = __shfl_xor_sync(0xffffffffu, m, o);
        float ol = __shfl_xor_sync(0xffffffffu, l, o);
        float nm = fmaxf(m, om);
        l = l*__expf(m-nm) + ol*__expf(om-nm);
        m = nm;
    }
    __shared__ float sm[4], sl[4];
    int lane=threadIdx.x&31, wid=threadIdx.x>>5;
    if (lane==0){ sm[wid]=m; sl[wid]=l; }
    __syncthreads();
    if (threadIdx.x==0){
        m=sm[0]; l=sl[0];
        for (int i=1;i<4;i++){
            float nm=fmaxf(m,sm[i]);
            l = l*__expf(m-nm)+sl[i]*__expf(sm[i]-nm);
            m = nm;
        }
        rowM[r]=m; rowL[r]=l;
    }
}

// ---------------- final residual LayerNorm -----------------------------------
__global__ __launch_bounds__(256) void ln_kernel(const float* __restrict__ x,
    const float* __restrict__ w, const float* __restrict__ b, float* __restrict__ out)
{
    __shared__ float xs[Hv];
    __shared__ float red[40];
    const size_t row = blockIdx.x;
    const float* xr = x + row*Hv;
    float partial = 0.f;
    for (int i=threadIdx.x;i<Hv;i+=256){ float v=xr[i]; xs[i]=v; partial+=v; }
    float mu = blockReduceSum(partial, red)*(1.f/Hv);
    float p2=0.f;
    for (int i=threadIdx.x;i<Hv;i+=256){ float d=xs[i]-mu; p2+=d*d; }
    float var = blockReduceSum(p2, red)*(1.f/Hv);
    float rs = rsqrtf(var+1e-12f);
    float* o = out + row*Hv;
    for (int i=threadIdx.x;i<Hv;i+=256) o[i] = (xs[i]-mu)*rs*w[i] + b[i];
}

// ---------------- launcher ----------------------------------------------------
extern "C" void kernel_launch(void* const* d_in, const int* in_sizes, int n_in,
                              void* d_out, int out_size)
{
    const float* hs  =(const float*)d_in[0];
    const float* am  =(const float*)d_in[1];
    const float* Wq  =(const float*)d_in[2];
    const float* bq  =(const float*)d_in[3];
    const float* Wk  =(const float*)d_in[4];
    const float* bk  =(const float*)d_in[5];
    const float* Wv  =(const float*)d_in[6];
    const float* bvb =(const float*)d_in[7];
    const float* Wg1 =(const float*)d_in[8];
    const float* bg1 =(const float*)d_in[9];
    const float* glnw=(const float*)d_in[10];
    const float* glnb=(const float*)d_in[11];
    const float* Wg2 =(const float*)d_in[12];
    const float* bg2 =(const float*)d_in[13];
    const float* Wo  =(const float*)d_in[14];
    const float* bo  =(const float*)d_in[15];
    const float* lnw =(const float*)d_in[16];
    const float* lnb =(const float*)d_in[17];

    float* out   = (float*)d_out;
    float* probs = out + (size_t)Bv*Sv*Hv;   // tuple order: (out, probs)

    bf16 *hsh,*hsl,*Wth,*Wtl,*Qh,*Ql,*Kh,*Kl,*Vth,*Vtl,*ctxh,*ctxl;
    float *preln,*gates,*rowM,*rowL;
    cudaGetSymbolAddress((void**)&hsh,  g_hsh);
    cudaGetSymbolAddress((void**)&hsl,  g_hsl);
    cudaGetSymbolAddress((void**)&Wth,  g_Wth);
    cudaGetSymbolAddress((void**)&Wtl,  g_Wtl);
    cudaGetSymbolAddress((void**)&Qh,   g_Qh);
    cudaGetSymbolAddress((void**)&Ql,   g_Ql);
    cudaGetSymbolAddress((void**)&Kh,   g_Kh);
    cudaGetSymbolAddress((void**)&Kl,   g_Kl);
    cudaGetSymbolAddress((void**)&Vth,  g_Vth);
    cudaGetSymbolAddress((void**)&Vtl,  g_Vtl);
    cudaGetSymbolAddress((void**)&ctxh, g_ctxh);
    cudaGetSymbolAddress((void**)&ctxl, g_ctxl);
    cudaGetSymbolAddress((void**)&preln,g_preln);
    cudaGetSymbolAddress((void**)&gates,g_gates);
    cudaGetSymbolAddress((void**)&rowM, g_rowM);
    cudaGetSymbolAddress((void**)&rowL, g_rowL);

    const size_t HH = (size_t)Hv*Hv;
    const int M = Bv*Sv;

    // prep: input split, weight transpose+split, gates
    int n4 = M*Hv/4;
    split_kernel<<<(n4+255)/256, 256>>>(hs, hsh, hsl, n4);
    wsplit_kernel<<<dim3(24,24,4), 256>>>(Wq, Wk, Wv, Wo);
    gate_kernel<<<M/8, 128>>>(hs, Wg1, bg1, glnw, glnb, Wg2, bg2, gates);

    // QKV projections (tensor core, split bf16)
    dim3 gProj(Hv/128, M/128, 1);
    mmagemm<0><<<gProj,256>>>(hsh,hsl,Hv,0, Wth       ,Wtl       ,Hv,0, bq , nullptr,nullptr, Qh ,Ql , nullptr, Hv);
    mmagemm<1><<<gProj,256>>>(hsh,hsl,Hv,0, Wth+HH    ,Wtl+HH    ,Hv,0, bk , nullptr,nullptr, Kh ,Kl , nullptr, Hv);
    mmagemm<2><<<gProj,256>>>(hsh,hsl,Hv,0, Wth+2*HH  ,Wtl+2*HH  ,Hv,0, bvb, nullptr,nullptr, Vth,Vtl, nullptr, Hv);

    // scores = (Q K^T)/8 * gate + mask  -> raw scores into probs region
    dim3 gScore(Sv/128, Sv/128, Bv*NHv);
    mmagemm<3><<<gScore,256>>>(Qh,Ql,DHv,(size_t)Sv*DHv, Kh,Kl,DHv,(size_t)Sv*DHv,
                               nullptr, gates, am, nullptr,nullptr, probs, DHv);

    // softmax stats over raw scores
    stats_kernel<<<Bv*NHv*Sv,128>>>(probs, rowM, rowL);

    // PV: normalize probs in-place + ctx (bf16 split)
    pv_kernel<<<dim3(Sv/128, Bv*NHv), 256>>>(probs, Vth, Vtl, rowM, rowL, ctxh, ctxl);

    // out projection + bias + residual, then LayerNorm
    mmagemm<4><<<gProj,256>>>(ctxh,ctxl,Hv,0, Wth+3*HH,Wtl+3*HH,Hv,0, bo, hs, nullptr,
                              nullptr,nullptr, preln, Hv);
    ln_kernel<<<M,256>>>(preln, lnw, lnb, out);
}

// round 3
// speedup vs baseline: 1.9760x; 1.3128x over previous
#include <cuda_runtime.h>
#include <cuda_bf16.h>

#define Bv 4
#define Sv 2048
#define Hv 768
#define NHv 12
#define DHv 64
#define WHv 128

typedef __nv_bfloat16 bf16;
typedef unsigned int u32;

// ---------------- scratch (static device globals) ---------------------------
__device__ bf16 g_hsh[(size_t)Bv*Sv*Hv];
__device__ bf16 g_hsl[(size_t)Bv*Sv*Hv];
__device__ bf16 g_Wth[(size_t)4*Hv*Hv];     // W^T hi, 4 weights (q,k,v,o)
__device__ bf16 g_Wtl[(size_t)4*Hv*Hv];     // W^T lo
__device__ bf16 g_Qh[(size_t)Bv*NHv*Sv*DHv];
__device__ bf16 g_Ql[(size_t)Bv*NHv*Sv*DHv];
__device__ bf16 g_Kh[(size_t)Bv*NHv*Sv*DHv];
__device__ bf16 g_Kl[(size_t)Bv*NHv*Sv*DHv];
__device__ bf16 g_Vth[(size_t)Bv*NHv*DHv*Sv];   // [z][dh][s]
__device__ bf16 g_Vtl[(size_t)Bv*NHv*DHv*Sv];
__device__ bf16 g_ctxh[(size_t)Bv*Sv*Hv];
__device__ bf16 g_ctxl[(size_t)Bv*Sv*Hv];
__device__ float g_preln[(size_t)Bv*Sv*Hv];
__device__ float g_gates[Bv*NHv*Sv];
__device__ float g_rowL[Bv*NHv*Sv];

// ---------------- mma / cp.async helpers -------------------------------------
__device__ __forceinline__ void mma16816(float& c0, float& c1, float& c2, float& c3,
                                         const u32 a[4], const u32 b[2]){
    asm volatile("mma.sync.aligned.m16n8k16.row.col.f32.bf16.bf16.f32 "
        "{%0,%1,%2,%3}, {%4,%5,%6,%7}, {%8,%9}, {%0,%1,%2,%3};"
        : "+f"(c0), "+f"(c1), "+f"(c2), "+f"(c3)
        : "r"(a[0]), "r"(a[1]), "r"(a[2]), "r"(a[3]), "r"(b[0]), "r"(b[1]));
}
__device__ __forceinline__ void cpa16(void* s, const void* g){
    asm volatile("cp.async.ca.shared.global [%0], [%1], 16;\n"
        :: "r"((u32)__cvta_generic_to_shared(s)), "l"(g));
}
#define CP_COMMIT() asm volatile("cp.async.commit_group;\n")
#define CP_WAIT0()  asm volatile("cp.async.wait_group 0;\n")
#define CP_WAIT1()  asm volatile("cp.async.wait_group 1;\n")

// ---------------- split / transpose prep kernels -----------------------------
__global__ __launch_bounds__(256) void split_kernel(const float* __restrict__ x,
    bf16* __restrict__ h, bf16* __restrict__ l, int n4)
{
    int i = blockIdx.x*256 + threadIdx.x;
    if (i >= n4) return;
    float4 v = ((const float4*)x)[i];
    __nv_bfloat162 h01 = __floats2bfloat162_rn(v.x, v.y);
    __nv_bfloat162 h23 = __floats2bfloat162_rn(v.z, v.w);
    __nv_bfloat162 l01 = __floats2bfloat162_rn(v.x-__low2float(h01), v.y-__high2float(h01));
    __nv_bfloat162 l23 = __floats2bfloat162_rn(v.z-__low2float(h23), v.w-__high2float(h23));
    ((__nv_bfloat162*)h)[i*2  ] = h01; ((__nv_bfloat162*)h)[i*2+1] = h23;
    ((__nv_bfloat162*)l)[i*2  ] = l01; ((__nv_bfloat162*)l)[i*2+1] = l23;
}

__global__ __launch_bounds__(256) void wsplit_kernel(
    const float* __restrict__ w0, const float* __restrict__ w1,
    const float* __restrict__ w2, const float* __restrict__ w3)
{
    __shared__ float t[32][33];
    const float* W = blockIdx.z==0 ? w0 : blockIdx.z==1 ? w1 : blockIdx.z==2 ? w2 : w3;
    bf16* oh = g_Wth + (size_t)blockIdx.z*Hv*Hv;
    bf16* ol = g_Wtl + (size_t)blockIdx.z*Hv*Hv;
    int k0 = blockIdx.y*32, n0 = blockIdx.x*32;
    int tx = threadIdx.x & 31, ty = threadIdx.x >> 5;   // (32,8)
    #pragma unroll
    for (int r=0;r<32;r+=8) t[ty+r][tx] = W[(size_t)(k0+ty+r)*Hv + n0+tx];
    __syncthreads();
    #pragma unroll
    for (int r=0;r<32;r+=8){
        float v = t[tx][ty+r];                 // = W[k0+tx][n0+ty+r]
        size_t idx = (size_t)(n0+ty+r)*Hv + k0+tx;
        bf16 h = __float2bfloat16(v);
        oh[idx] = h;
        ol[idx] = __float2bfloat16(v - __bfloat162float(h));
    }
}

// ---------------- double-buffered bf16-split tensor-core GEMM ----------------
// C[M,N] = A[M,K] @ B^T[N,K]   (3 mma terms: AhBh + AhBl + AlBh)
// MODE 0/1: QK proj -> bf16 pair [b,nh,s,dh], +bias
// MODE 2: V proj    -> bf16 pair [b,nh,dh,s] (transposed), +bias
// MODE 3: scores    -> exp(gate*qk/8 + maskbias) fp32 (unnormalized) + rowL atomics
// MODE 4: Wo proj   -> preln fp32, +bias +resid
template<int MODE>
__global__ __launch_bounds__(256) void mmagemm(
    const bf16* __restrict__ Ah, const bf16* __restrict__ Al, int lda, size_t sA,
    const bf16* __restrict__ Bh, const bf16* __restrict__ Bl, int ldb, size_t sB,
    const float* __restrict__ bias,
    const float* __restrict__ e1,   // gates (MODE3) / resid (MODE4)
    const float* __restrict__ e2,   // attention_mask (MODE3)
    bf16* __restrict__ Oh, bf16* __restrict__ Ol, float* __restrict__ Of,
    float* __restrict__ Ex,         // rowL (MODE3)
    int K)
{
    constexpr int LDSK = 40;
    constexpr int BUF  = 128*LDSK;
    extern __shared__ bf16 smem[];
    bf16* sAh = smem;
    bf16* sAl = sAh + 2*BUF;
    bf16* sBh = sAl + 2*BUF;
    bf16* sBl = sBh + 2*BUF;

    const int tid  = threadIdx.x, lane = tid & 31, warp = tid >> 5;
    const int grp  = lane >> 2,   tig  = lane & 3;
    const int z    = blockIdx.z;
    const int row0 = blockIdx.y*128, col0 = blockIdx.x*128;
    const bf16* A_h = Ah + (size_t)z*sA;
    const bf16* A_l = Al + (size_t)z*sA;
    const bf16* B_h = Bh + (size_t)z*sB;
    const bf16* B_l = Bl + (size_t)z*sB;
    const int warpM = (warp>>2)*64, warpN = (warp&3)*32;
    const int lr = tid>>2, lcc = (tid&3)*8;

    float c[4][4][4];
    #pragma unroll
    for (int i=0;i<4;i++)
        #pragma unroll
        for (int j=0;j<4;j++)
            #pragma unroll
            for (int r=0;r<4;r++) c[i][j][r]=0.f;

    // async load of one k-tile into stage st
    auto load_tile = [&](int kt, int st){
        const int k0 = kt*32;
        bf16* dAh = sAh + st*BUF; bf16* dAl = sAl + st*BUF;
        bf16* dBh = sBh + st*BUF; bf16* dBl = sBl + st*BUF;
        #pragma unroll
        for (int t=0;t<2;t++){
            int r = lr + t*64;
            cpa16(&dAh[r*LDSK+lcc], &A_h[(size_t)(row0+r)*lda + k0+lcc]);
            cpa16(&dAl[r*LDSK+lcc], &A_l[(size_t)(row0+r)*lda + k0+lcc]);
            cpa16(&dBh[r*LDSK+lcc], &B_h[(size_t)(col0+r)*ldb + k0+lcc]);
            cpa16(&dBl[r*LDSK+lcc], &B_l[(size_t)(col0+r)*ldb + k0+lcc]);
        }
    };

    const int KT = K/32;
    load_tile(0, 0); CP_COMMIT();

    for (int kt=0; kt<KT; kt++){
        const int st = kt & 1;
        if (kt+1 < KT){ load_tile(kt+1, st^1); CP_COMMIT(); CP_WAIT1(); }
        else          { CP_WAIT0(); }
        __syncthreads();
        const bf16* pAh = sAh + st*BUF; const bf16* pAl = sAl + st*BUF;
        const bf16* pBh = sBh + st*BUF; const bf16* pBl = sBl + st*BUF;
        #pragma unroll
        for (int ks=0;ks<32;ks+=16){
            u32 a[4][4], bh_[4][2], bl_[4][2];
            #pragma unroll
            for (int j=0;j<4;j++){
                int n = (warpN + j*8 + grp)*LDSK + ks + tig*2;
                bh_[j][0]=*(u32*)&pBh[n]; bh_[j][1]=*(u32*)&pBh[n+8];
                bl_[j][0]=*(u32*)&pBl[n]; bl_[j][1]=*(u32*)&pBl[n+8];
            }
            #pragma unroll
            for (int i=0;i<4;i++){
                int r = (warpM + i*16 + grp)*LDSK + ks + tig*2;
                a[i][0]=*(u32*)&pAh[r];          a[i][1]=*(u32*)&pAh[r+8*LDSK];
                a[i][2]=*(u32*)&pAh[r+8];        a[i][3]=*(u32*)&pAh[r+8*LDSK+8];
            }
            #pragma unroll
            for (int i=0;i<4;i++)
                #pragma unroll
                for (int j=0;j<4;j++){
                    mma16816(c[i][j][0],c[i][j][1],c[i][j][2],c[i][j][3], a[i], bh_[j]);
                    mma16816(c[i][j][0],c[i][j][1],c[i][j][2],c[i][j][3], a[i], bl_[j]);
                }
            #pragma unroll
            for (int i=0;i<4;i++){
                int r = (warpM + i*16 + grp)*LDSK + ks + tig*2;
                a[i][0]=*(u32*)&pAl[r];          a[i][1]=*(u32*)&pAl[r+8*LDSK];
                a[i][2]=*(u32*)&pAl[r+8];        a[i][3]=*(u32*)&pAl[r+8*LDSK+8];
            }
            #pragma unroll
            for (int i=0;i<4;i++)
                #pragma unroll
                for (int j=0;j<4;j++)
                    mma16816(c[i][j][0],c[i][j][1],c[i][j][2],c[i][j][3], a[i], bh_[j]);
        }
        __syncthreads();
    }

    if (MODE==3){
        // scores: write exp(unnormalized) + per-row partial sums -> atomicAdd rowL
        float* rowLp = Ex + (size_t)z*Sv;
        const float* mk = e2 + (size_t)(z/NHv)*Sv;
        float* Oz = Of + (size_t)z*Sv*Sv;
        #pragma unroll
        for (int i=0;i<4;i++){
            #pragma unroll
            for (int half=0; half<2; half++){
                int r = row0 + warpM + i*16 + grp + half*8;
                float g = e1[(size_t)z*Sv + r]*0.125f;
                float rs = 0.f;
                #pragma unroll
                for (int j=0;j<4;j++){
                    int cn = col0 + warpN + j*8 + tig*2;
                    float s0 = c[i][j][half*2  ]*g + (1.f-mk[cn  ])*-10000.f;
                    float s1 = c[i][j][half*2+1]*g + (1.f-mk[cn+1])*-10000.f;
                    float2 o; o.x = __expf(s0); o.y = __expf(s1);
                    *(float2*)(Oz + (size_t)r*Sv + cn) = o;
                    rs += o.x + o.y;
                }
                rs += __shfl_xor_sync(0xffffffffu, rs, 1);
                rs += __shfl_xor_sync(0xffffffffu, rs, 2);
                if (tig==0) atomicAdd(&rowLp[r], rs);
            }
        }
    } else {
        #pragma unroll
        for (int i=0;i<4;i++){
            #pragma unroll
            for (int j=0;j<4;j++){
                int cn = col0 + warpN + j*8 + tig*2;
                #pragma unroll
                for (int half=0; half<2; half++){
                    int r = row0 + warpM + i*16 + grp + half*8;
                    float v0 = c[i][j][half*2], v1 = c[i][j][half*2+1];
                    if (MODE==0 || MODE==1){
                        float x0 = v0 + bias[cn], x1 = v1 + bias[cn+1];
                        int b=r/Sv, s=r-b*Sv, nh=cn>>6, dh=cn&63;
                        size_t idx = (((size_t)(b*NHv+nh)*Sv+s)<<6)+dh;
                        __nv_bfloat162 h = __floats2bfloat162_rn(x0,x1);
                        __nv_bfloat162 l = __floats2bfloat162_rn(x0-__low2float(h), x1-__high2float(h));
                        *(__nv_bfloat162*)(Oh+idx)=h;
                        *(__nv_bfloat162*)(Ol+idx)=l;
                    } else if (MODE==2){
                        float x0 = v0 + bias[cn], x1 = v1 + bias[cn+1];
                        int b=r/Sv, s=r-b*Sv, nh=cn>>6, dh=cn&63;
                        size_t i0 = ((size_t)(b*NHv+nh)*DHv+dh)*Sv + s;
                        bf16 h0=__float2bfloat16(x0);
                        Oh[i0]=h0; Ol[i0]=__float2bfloat16(x0-__bfloat162float(h0));
                        bf16 h1=__float2bfloat16(x1);
                        Oh[i0+Sv]=h1; Ol[i0+Sv]=__float2bfloat16(x1-__bfloat162float(h1));
                    } else {
                        size_t idx = (size_t)r*Hv + cn;
                        float2 o;
                        o.x = v0 + bias[cn  ] + e1[idx  ];
                        o.y = v1 + bias[cn+1] + e1[idx+1];
                        *(float2*)(Of+idx) = o;
                    }
                }
            }
        }
    }
}

// ---------------- PV: normalize exp in place + ctx = P@V (bf16 split out) ----
__global__ __launch_bounds__(256) void pv_kernel(
    float* __restrict__ probs,                 // in: unnormalized exp, out: probs
    const bf16* __restrict__ Vth, const bf16* __restrict__ Vtl,
    const float* __restrict__ rowL,
    bf16* __restrict__ ctxh, bf16* __restrict__ ctxl)
{
    constexpr int LDSK = 40;
    __shared__ bf16 sPh[128*LDSK], sPl[128*LDSK], sVh[64*LDSK], sVl[64*LDSK];
    __shared__ float sI[128];
    const int tid = threadIdx.x, lane = tid & 31, warp = tid >> 5;
    const int grp = lane >> 2, tig = lane & 3;
    const int z = blockIdx.y, q0 = blockIdx.x*128;
    if (tid < 128)
        sI[tid] = 1.f / rowL[(size_t)z*Sv + q0 + tid];
    __syncthreads();
    const int warpM = (warp>>1)*32, warpN = (warp&1)*32;
    float c[2][4][4];
    #pragma unroll
    for (int i=0;i<2;i++)
        #pragma unroll
        for (int j=0;j<4;j++)
            #pragma unroll
            for (int r=0;r<4;r++) c[i][j][r]=0.f;

    float* Pz = probs + (size_t)z*Sv*Sv;
    const bf16* Vh_ = Vth + (size_t)z*DHv*Sv;
    const bf16* Vl_ = Vtl + (size_t)z*DHv*Sv;

    for (int k0=0;k0<Sv;k0+=32){
        {   // V tile async
            int r = tid>>2, cc = (tid&3)*8;
            size_t g = (size_t)r*Sv + k0 + cc;
            cpa16(&sVh[r*LDSK+cc], &Vh_[g]);
            cpa16(&sVl[r*LDSK+cc], &Vl_[g]);
        }
        CP_COMMIT();
        #pragma unroll
        for (int t=0;t<4;t++){
            int ch = tid + t*256;
            int r = ch>>3, cc = (ch&7)*4;
            size_t g = (size_t)(q0+r)*Sv + k0 + cc;
            float4 v = *(float4*)&Pz[g];
            float inv = sI[r];
            float p0=v.x*inv, p1=v.y*inv, p2=v.z*inv, p3=v.w*inv;
            float4 pv; pv.x=p0; pv.y=p1; pv.z=p2; pv.w=p3;
            *(float4*)&Pz[g] = pv;
            __nv_bfloat162 h01=__floats2bfloat162_rn(p0,p1), h23=__floats2bfloat162_rn(p2,p3);
            __nv_bfloat162 l01=__floats2bfloat162_rn(p0-__low2float(h01), p1-__high2float(h01));
            __nv_bfloat162 l23=__floats2bfloat162_rn(p2-__low2float(h23), p3-__high2float(h23));
            *(__nv_bfloat162*)&sPh[r*LDSK+cc  ]=h01;
            *(__nv_bfloat162*)&sPh[r*LDSK+cc+2]=h23;
            *(__nv_bfloat162*)&sPl[r*LDSK+cc  ]=l01;
            *(__nv_bfloat162*)&sPl[r*LDSK+cc+2]=l23;
        }
        CP_WAIT0();
        __syncthreads();
        #pragma unroll
        for (int ks=0;ks<32;ks+=16){
            u32 a[2][4], bh_[4][2], bl_[4][2];
            #pragma unroll
            for (int j=0;j<4;j++){
                int n = (warpN + j*8 + grp)*LDSK + ks + tig*2;
                bh_[j][0]=*(u32*)&sVh[n]; bh_[j][1]=*(u32*)&sVh[n+8];
                bl_[j][0]=*(u32*)&sVl[n]; bl_[j][1]=*(u32*)&sVl[n+8];
            }
            #pragma unroll
            for (int i=0;i<2;i++){
                int r = (warpM + i*16 + grp)*LDSK + ks + tig*2;
                a[i][0]=*(u32*)&sPh[r];       a[i][1]=*(u32*)&sPh[r+8*LDSK];
                a[i][2]=*(u32*)&sPh[r+8];     a[i][3]=*(u32*)&sPh[r+8*LDSK+8];
            }
            #pragma unroll
            for (int i=0;i<2;i++)
                #pragma unroll
                for (int j=0;j<4;j++){
                    mma16816(c[i][j][0],c[i][j][1],c[i][j][2],c[i][j][3], a[i], bh_[j]);
                    mma16816(c[i][j][0],c[i][j][1],c[i][j][2],c[i][j][3], a[i], bl_[j]);
                }
            #pragma unroll
            for (int i=0;i<2;i++){
                int r = (warpM + i*16 + grp)*LDSK + ks + tig*2;
                a[i][0]=*(u32*)&sPl[r];       a[i][1]=*(u32*)&sPl[r+8*LDSK];
                a[i][2]=*(u32*)&sPl[r+8];     a[i][3]=*(u32*)&sPl[r+8*LDSK+8];
            }
            #pragma unroll
            for (int i=0;i<2;i++)
                #pragma unroll
                for (int j=0;j<4;j++)
                    mma16816(c[i][j][0],c[i][j][1],c[i][j][2],c[i][j][3], a[i], bh_[j]);
        }
        __syncthreads();
    }

    const int b = z/NHv, nh = z%NHv;
    #pragma unroll
    for (int i=0;i<2;i++){
        #pragma unroll
        for (int j=0;j<4;j++){
            int dh = warpN + j*8 + tig*2;
            #pragma unroll
            for (int half=0; half<2; half++){
                int s = q0 + warpM + i*16 + grp + half*8;
                float x0 = c[i][j][half*2], x1 = c[i][j][half*2+1];
                size_t idx = ((size_t)b*Sv + s)*Hv + nh*DHv + dh;
                __nv_bfloat162 h = __floats2bfloat162_rn(x0,x1);
                __nv_bfloat162 l = __floats2bfloat162_rn(x0-__low2float(h), x1-__high2float(h));
                *(__nv_bfloat162*)(ctxh+idx)=h;
                *(__nv_bfloat162*)(ctxl+idx)=l;
            }
        }
    }
}

// ---------------- helpers ----------------------------------------------------
__device__ __forceinline__ float blockReduceSum(float v, float* red){
    #pragma unroll
    for (int o=16;o;o>>=1) v += __shfl_xor_sync(0xffffffffu, v, o);
    const int lane = threadIdx.x & 31, wid = threadIdx.x >> 5;
    const int nw = blockDim.x >> 5;
    __syncthreads();
    if (lane==0) red[wid]=v;
    __syncthreads();
    if (threadIdx.x==0){
        float s=0.f;
        for (int i=0;i<nw;i++) s+=red[i];
        red[32]=s;
    }
    __syncthreads();
    return red[32];
}

// ---------------- wormhole gate ----------------------------------------------
__global__ __launch_bounds__(128) void gate_kernel(
    const float* __restrict__ hs, const float* __restrict__ Wg1, const float* __restrict__ bg1,
    const float* __restrict__ glnw, const float* __restrict__ glnb,
    const float* __restrict__ Wg2, const float* __restrict__ bg2,
    float* __restrict__ gates)
{
    const int ROWS=8;
    __shared__ float hs_s[ROWS*Hv];
    __shared__ float g_s[ROWS][WHv+4];
    __shared__ float red[40];
    const int tid = threadIdx.x;
    const size_t rowbase = (size_t)blockIdx.x*ROWS;

    for (int i=tid;i<ROWS*Hv;i+=128) hs_s[i] = hs[rowbase*Hv + i];
    __syncthreads();

    float acc[ROWS];
    #pragma unroll
    for (int r=0;r<ROWS;r++) acc[r]=bg1[tid];
    for (int h=0;h<Hv;h++){
        float wv = Wg1[h*WHv + tid];
        #pragma unroll
        for (int r=0;r<ROWS;r++) acc[r] = fmaf(hs_s[r*Hv+h], wv, acc[r]);
    }
    float lw = glnw[tid], lb = glnb[tid];
    #pragma unroll
    for (int r=0;r<ROWS;r++){
        float mu  = blockReduceSum(acc[r], red) * (1.f/WHv);
        float d   = acc[r]-mu;
        float var = blockReduceSum(d*d, red) * (1.f/WHv);
        float gv  = d*rsqrtf(var+1e-12f)*lw + lb;
        g_s[r][tid] = fmaxf(gv, 0.f);
    }
    __syncthreads();
    if (tid < ROWS*NHv){
        int r = tid/NHv, o = tid%NHv;
        float s = bg2[o];
        for (int c=0;c<WHv;c++) s = fmaf(g_s[r][c], Wg2[c*NHv+o], s);
        float gate = 1.f/(1.f+__expf(-s));
        size_t row = rowbase + r;
        int b = (int)(row/Sv), sq = (int)(row%Sv);
        gates[((size_t)(b*NHv+o))*Sv + sq] = gate;
    }
}

// ---------------- final residual LayerNorm -----------------------------------
__global__ __launch_bounds__(256) void ln_kernel(const float* __restrict__ x,
    const float* __restrict__ w, const float* __restrict__ b, float* __restrict__ out)
{
    __shared__ float xs[Hv];
    __shared__ float red[40];
    const size_t row = blockIdx.x;
    const float* xr = x + row*Hv;
    float partial = 0.f;
    for (int i=threadIdx.x;i<Hv;i+=256){ float v=xr[i]; xs[i]=v; partial+=v; }
    float mu = blockReduceSum(partial, red)*(1.f/Hv);
    float p2=0.f;
    for (int i=threadIdx.x;i<Hv;i+=256){ float d=xs[i]-mu; p2+=d*d; }
    float var = blockReduceSum(p2, red)*(1.f/Hv);
    float rs = rsqrtf(var+1e-12f);
    float* o = out + row*Hv;
    for (int i=threadIdx.x;i<Hv;i+=256) o[i] = (xs[i]-mu)*rs*w[i] + b[i];
}

// ---------------- launcher ----------------------------------------------------
extern "C" void kernel_launch(void* const* d_in, const int* in_sizes, int n_in,
                              void* d_out, int out_size)
{
    const float* hs  =(const float*)d_in[0];
    const float* am  =(const float*)d_in[1];
    const float* Wq  =(const float*)d_in[2];
    const float* bq  =(const float*)d_in[3];
    const float* Wk  =(const float*)d_in[4];
    const float* bk  =(const float*)d_in[5];
    const float* Wv  =(const float*)d_in[6];
    const float* bvb =(const float*)d_in[7];
    const float* Wg1 =(const float*)d_in[8];
    const float* bg1 =(const float*)d_in[9];
    const float* glnw=(const float*)d_in[10];
    const float* glnb=(const float*)d_in[11];
    const float* Wg2 =(const float*)d_in[12];
    const float* bg2 =(const float*)d_in[13];
    const float* Wo  =(const float*)d_in[14];
    const float* bo  =(const float*)d_in[15];
    const float* lnw =(const float*)d_in[16];
    const float* lnb =(const float*)d_in[17];

    float* out   = (float*)d_out;
    float* probs = out + (size_t)Bv*Sv*Hv;   // tuple order: (out, probs)

    bf16 *hsh,*hsl,*Wth,*Wtl,*Qh,*Ql,*Kh,*Kl,*Vth,*Vtl,*ctxh,*ctxl;
    float *preln,*gates,*rowL;
    cudaGetSymbolAddress((void**)&hsh,  g_hsh);
    cudaGetSymbolAddress((void**)&hsl,  g_hsl);
    cudaGetSymbolAddress((void**)&Wth,  g_Wth);
    cudaGetSymbolAddress((void**)&Wtl,  g_Wtl);
    cudaGetSymbolAddress((void**)&Qh,   g_Qh);
    cudaGetSymbolAddress((void**)&Ql,   g_Ql);
    cudaGetSymbolAddress((void**)&Kh,   g_Kh);
    cudaGetSymbolAddress((void**)&Kl,   g_Kl);
    cudaGetSymbolAddress((void**)&Vth,  g_Vth);
    cudaGetSymbolAddress((void**)&Vtl,  g_Vtl);
    cudaGetSymbolAddress((void**)&ctxh, g_ctxh);
    cudaGetSymbolAddress((void**)&ctxl, g_ctxl);
    cudaGetSymbolAddress((void**)&preln,g_preln);
    cudaGetSymbolAddress((void**)&gates,g_gates);
    cudaGetSymbolAddress((void**)&rowL, g_rowL);

    const size_t HH = (size_t)Hv*Hv;
    const int M = Bv*Sv;
    const int SMEM_GEMM = 2*4*128*40*(int)sizeof(bf16);   // 81920 B

    cudaFuncSetAttribute(mmagemm<0>, cudaFuncAttributeMaxDynamicSharedMemorySize, SMEM_GEMM);
    cudaFuncSetAttribute(mmagemm<1>, cudaFuncAttributeMaxDynamicSharedMemorySize, SMEM_GEMM);
    cudaFuncSetAttribute(mmagemm<2>, cudaFuncAttributeMaxDynamicSharedMemorySize, SMEM_GEMM);
    cudaFuncSetAttribute(mmagemm<3>, cudaFuncAttributeMaxDynamicSharedMemorySize, SMEM_GEMM);
    cudaFuncSetAttribute(mmagemm<4>, cudaFuncAttributeMaxDynamicSharedMemorySize, SMEM_GEMM);

    // prep: zero rowL, input split, weight transpose+split, gates
    cudaMemsetAsync(rowL, 0, (size_t)Bv*NHv*Sv*sizeof(float));
    int n4 = M*Hv/4;
    split_kernel<<<(n4+255)/256, 256>>>(hs, hsh, hsl, n4);
    wsplit_kernel<<<dim3(24,24,4), 256>>>(Wq, Wk, Wv, Wo);
    gate_kernel<<<M/8, 128>>>(hs, Wg1, bg1, glnw, glnb, Wg2, bg2, gates);

    // QKV projections
    dim3 gProj(Hv/128, M/128, 1);
    mmagemm<0><<<gProj,256,SMEM_GEMM>>>(hsh,hsl,Hv,0, Wth     ,Wtl     ,Hv,0, bq , nullptr,nullptr, Qh ,Ql , nullptr, nullptr, Hv);
    mmagemm<1><<<gProj,256,SMEM_GEMM>>>(hsh,hsl,Hv,0, Wth+HH  ,Wtl+HH  ,Hv,0, bk , nullptr,nullptr, Kh ,Kl , nullptr, nullptr, Hv);
    mmagemm<2><<<gProj,256,SMEM_GEMM>>>(hsh,hsl,Hv,0, Wth+2*HH,Wtl+2*HH,Hv,0, bvb, nullptr,nullptr, Vth,Vtl, nullptr, nullptr, Hv);

    // scores -> exp(gate*qk/8 + mask) unnormalized into probs region + rowL sums
    dim3 gScore(Sv/128, Sv/128, Bv*NHv);
    mmagemm<3><<<gScore,256,SMEM_GEMM>>>(Qh,Ql,DHv,(size_t)Sv*DHv, Kh,Kl,DHv,(size_t)Sv*DHv,
                                         nullptr, gates, am, nullptr,nullptr, probs, rowL, DHv);

    // PV: normalize in place + ctx (bf16 split)
    pv_kernel<<<dim3(Sv/128, Bv*NHv), 256>>>(probs, Vth, Vtl, rowL, ctxh, ctxl);

    // out projection + bias + residual, then LayerNorm
    mmagemm<4><<<gProj,256,SMEM_GEMM>>>(ctxh,ctxl,Hv,0, Wth+3*HH,Wtl+3*HH,Hv,0, bo, hs, nullptr,
                                        nullptr,nullptr, preln, nullptr, Hv);
    ln_kernel<<<M,256>>>(preln, lnw, lnb, out);
}

// round 7
// speedup vs baseline: 2.6466x; 1.3394x over previous
#include <cuda_runtime.h>
#include <cuda_bf16.h>

#define Bv 4
#define Sv 2048
#define Hv 768
#define NHv 12
#define DHv 64
#define WHv 128

typedef __nv_bfloat16 bf16;
typedef unsigned int u32;

// ---------------- scratch (static device globals) ---------------------------
__device__ bf16 g_hsh[(size_t)Bv*Sv*Hv];
__device__ bf16 g_hsl[(size_t)Bv*Sv*Hv];
__device__ bf16 g_Wth[(size_t)4*Hv*Hv];     // W^T hi, rows: [q|k|v|o] stacked
__device__ bf16 g_Wtl[(size_t)4*Hv*Hv];     // W^T lo
__device__ bf16 g_Qh[(size_t)Bv*NHv*Sv*DHv];
__device__ bf16 g_Ql[(size_t)Bv*NHv*Sv*DHv];
__device__ bf16 g_Kh[(size_t)Bv*NHv*Sv*DHv];
__device__ bf16 g_Kl[(size_t)Bv*NHv*Sv*DHv];
__device__ bf16 g_Vth[(size_t)Bv*NHv*DHv*Sv];   // [z][dh][s]
__device__ bf16 g_Vtl[(size_t)Bv*NHv*DHv*Sv];
__device__ bf16 g_ctxh[(size_t)Bv*Sv*Hv];
__device__ bf16 g_ctxl[(size_t)Bv*Sv*Hv];
__device__ float g_preln[(size_t)Bv*Sv*Hv];
__device__ float g_gates[Bv*NHv*Sv];
__device__ float g_rowL[Bv*NHv*Sv];

// ---------------- asm helpers ------------------------------------------------
__device__ __forceinline__ void mma16816(float& c0, float& c1, float& c2, float& c3,
                                         const u32 a[4], const u32 b[2]){
    asm volatile("mma.sync.aligned.m16n8k16.row.col.f32.bf16.bf16.f32 "
        "{%0,%1,%2,%3}, {%4,%5,%6,%7}, {%8,%9}, {%0,%1,%2,%3};"
        : "+f"(c0), "+f"(c1), "+f"(c2), "+f"(c3)
        : "r"(a[0]), "r"(a[1]), "r"(a[2]), "r"(a[3]), "r"(b[0]), "r"(b[1]));
}
__device__ __forceinline__ void cpa16(void* s, const void* g){
    asm volatile("cp.async.ca.shared.global [%0], [%1], 16;\n"
        :: "r"((u32)__cvta_generic_to_shared(s)), "l"(g));
}
__device__ __forceinline__ void ldm_x4(u32& r0,u32& r1,u32& r2,u32& r3, const void* p){
    asm volatile("ldmatrix.sync.aligned.m8n8.x4.shared.b16 {%0,%1,%2,%3}, [%4];"
        : "=r"(r0),"=r"(r1),"=r"(r2),"=r"(r3)
        : "r"((u32)__cvta_generic_to_shared(p)));
}
#define CP_COMMIT() asm volatile("cp.async.commit_group;\n")
#define CP_WAIT0()  asm volatile("cp.async.wait_group 0;\n")
#define CP_WAIT1()  asm volatile("cp.async.wait_group 1;\n")

// ---------------- split / transpose prep kernels -----------------------------
__global__ __launch_bounds__(256) void split_kernel(const float* __restrict__ x,
    bf16* __restrict__ h, bf16* __restrict__ l, int n4)
{
    int i = blockIdx.x*256 + threadIdx.x;
    if (i >= n4) return;
    float4 v = ((const float4*)x)[i];
    __nv_bfloat162 h01 = __floats2bfloat162_rn(v.x, v.y);
    __nv_bfloat162 h23 = __floats2bfloat162_rn(v.z, v.w);
    __nv_bfloat162 l01 = __floats2bfloat162_rn(v.x-__low2float(h01), v.y-__high2float(h01));
    __nv_bfloat162 l23 = __floats2bfloat162_rn(v.z-__low2float(h23), v.w-__high2float(h23));
    ((__nv_bfloat162*)h)[i*2  ] = h01; ((__nv_bfloat162*)h)[i*2+1] = h23;
    ((__nv_bfloat162*)l)[i*2  ] = l01; ((__nv_bfloat162*)l)[i*2+1] = l23;
}

__global__ __launch_bounds__(256) void wsplit_kernel(
    const float* __restrict__ w0, const float* __restrict__ w1,
    const float* __restrict__ w2, const float* __restrict__ w3)
{
    __shared__ float t[32][33];
    const float* W = blockIdx.z==0 ? w0 : blockIdx.z==1 ? w1 : blockIdx.z==2 ? w2 : w3;
    bf16* oh = g_Wth + (size_t)blockIdx.z*Hv*Hv;
    bf16* ol = g_Wtl + (size_t)blockIdx.z*Hv*Hv;
    int k0 = blockIdx.y*32, n0 = blockIdx.x*32;
    int tx = threadIdx.x & 31, ty = threadIdx.x >> 5;   // (32,8)
    #pragma unroll
    for (int r=0;r<32;r+=8) t[ty+r][tx] = W[(size_t)(k0+ty+r)*Hv + n0+tx];
    __syncthreads();
    #pragma unroll
    for (int r=0;r<32;r+=8){
        float v = t[tx][ty+r];                 // = W[k0+tx][n0+ty+r]
        size_t idx = (size_t)(n0+ty+r)*Hv + k0+tx;
        bf16 h = __float2bfloat16(v);
        oh[idx] = h;
        ol[idx] = __float2bfloat16(v - __bfloat162float(h));
    }
}

// ---------------- bf16-split tensor-core GEMM (ldmatrix + cp.async pipe) -----
// C[M,N] = A[M,K] @ B^T[N,K]   (3 mma terms: AhBh + AhBl + AlBh)
// MODE 3: scores -> exp(gate*qk/8 + maskbias) fp32 (unnormalized) + rowL atomics
// MODE 4: Wo proj -> preln fp32, +bias +resid
// MODE 5: fused QKV proj (N = 3*H): Q/K -> [b,nh,s,dh] bf16 pair; V -> [b,nh,dh,s]
template<int MODE>
__global__ __launch_bounds__(256,2) void mmagemm(
    const bf16* __restrict__ Ah, const bf16* __restrict__ Al, int lda, size_t sA,
    const bf16* __restrict__ Bh, const bf16* __restrict__ Bl, int ldb, size_t sB,
    const float* __restrict__ bias0, const float* __restrict__ bias1,
    const float* __restrict__ bias2,
    const float* __restrict__ e1,   // gates (M3) / resid (M4)
    const float* __restrict__ e2,   // attention_mask (M3)
    bf16* __restrict__ Qh_, bf16* __restrict__ Ql_,
    bf16* __restrict__ Kh_, bf16* __restrict__ Kl_,
    bf16* __restrict__ Vh_, bf16* __restrict__ Vl_,
    float* __restrict__ Of, float* __restrict__ Ex,
    int K)
{
    constexpr int LDSK = 40;
    constexpr int BUF  = 128*LDSK;
    extern __shared__ bf16 smem[];
    bf16* sAh = smem;
    bf16* sAl = sAh + 2*BUF;
    bf16* sBh = sAl + 2*BUF;
    bf16* sBl = sBh + 2*BUF;

    const int tid  = threadIdx.x, lane = tid & 31, warp = tid >> 5;
    const int grp  = lane >> 2,   tig  = lane & 3;
    const int z    = blockIdx.z;
    const int row0 = blockIdx.y*128, col0 = blockIdx.x*128;
    const bf16* A_h = Ah + (size_t)z*sA;
    const bf16* A_l = Al + (size_t)z*sA;
    const bf16* B_h = Bh + (size_t)z*sB;
    const bf16* B_l = Bl + (size_t)z*sB;
    const int warpM = (warp>>2)*64, warpN = (warp&3)*32;
    const int lr = tid>>2, lcc = (tid&3)*8;
    // ldmatrix lane addressing
    const int aRow  = lane & 15,        aCol8 = (lane >> 4) * 8;
    const int bRow  = (lane & 7) + ((lane >> 4) << 3);
    const int bCol8 = ((lane >> 3) & 1) * 8;

    float c[4][4][4];
    #pragma unroll
    for (int i=0;i<4;i++)
        #pragma unroll
        for (int j=0;j<4;j++)
            #pragma unroll
            for (int r=0;r<4;r++) c[i][j][r]=0.f;

    auto load_tile = [&](int kt, int st){
        const int k0 = kt*32;
        bf16* dAh = sAh + st*BUF; bf16* dAl = sAl + st*BUF;
        bf16* dBh = sBh + st*BUF; bf16* dBl = sBl + st*BUF;
        #pragma unroll
        for (int t=0;t<2;t++){
            int r = lr + t*64;
            cpa16(&dAh[r*LDSK+lcc], &A_h[(size_t)(row0+r)*lda + k0+lcc]);
            cpa16(&dAl[r*LDSK+lcc], &A_l[(size_t)(row0+r)*lda + k0+lcc]);
            cpa16(&dBh[r*LDSK+lcc], &B_h[(size_t)(col0+r)*ldb + k0+lcc]);
            cpa16(&dBl[r*LDSK+lcc], &B_l[(size_t)(col0+r)*ldb + k0+lcc]);
        }
    };

    const int KT = K/32;
    load_tile(0, 0); CP_COMMIT();

    for (int kt=0; kt<KT; kt++){
        const int st = kt & 1;
        __syncthreads();                       // prev compute on st^1 done (WAR)
        if (kt+1 < KT){ load_tile(kt+1, st^1); CP_COMMIT(); CP_WAIT1(); }
        else          { CP_WAIT0(); }
        __syncthreads();                       // tile st visible to all
        const bf16* pAh = sAh + st*BUF; const bf16* pAl = sAl + st*BUF;
        const bf16* pBh = sBh + st*BUF; const bf16* pBl = sBl + st*BUF;
        #pragma unroll
        for (int ks=0;ks<32;ks+=16){
            u32 a[4][4], b_h[4][2], b_l[4][2];
            #pragma unroll
            for (int jj=0; jj<4; jj+=2){
                ldm_x4(b_h[jj][0], b_h[jj][1], b_h[jj+1][0], b_h[jj+1][1],
                       &pBh[(warpN + jj*8 + bRow)*LDSK + ks + bCol8]);
                ldm_x4(b_l[jj][0], b_l[jj][1], b_l[jj+1][0], b_l[jj+1][1],
                       &pBl[(warpN + jj*8 + bRow)*LDSK + ks + bCol8]);
            }
            #pragma unroll
            for (int i=0;i<4;i++)
                ldm_x4(a[i][0],a[i][1],a[i][2],a[i][3],
                       &pAh[(warpM + i*16 + aRow)*LDSK + ks + aCol8]);
            #pragma unroll
            for (int i=0;i<4;i++)
                #pragma unroll
                for (int j=0;j<4;j++){
                    mma16816(c[i][j][0],c[i][j][1],c[i][j][2],c[i][j][3], a[i], b_h[j]);
                    mma16816(c[i][j][0],c[i][j][1],c[i][j][2],c[i][j][3], a[i], b_l[j]);
                }
            #pragma unroll
            for (int i=0;i<4;i++)
                ldm_x4(a[i][0],a[i][1],a[i][2],a[i][3],
                       &pAl[(warpM + i*16 + aRow)*LDSK + ks + aCol8]);
            #pragma unroll
            for (int i=0;i<4;i++)
                #pragma unroll
                for (int j=0;j<4;j++)
                    mma16816(c[i][j][0],c[i][j][1],c[i][j][2],c[i][j][3], a[i], b_h[j]);
        }
    }

    if (MODE==3){
        float* rowLp = Ex + (size_t)z*Sv;
        const float* mk = e2 + (size_t)(z/NHv)*Sv;
        float* Oz = Of + (size_t)z*Sv*Sv;
        #pragma unroll
        for (int i=0;i<4;i++){
            #pragma unroll
            for (int half=0; half<2; half++){
                int r = row0 + warpM + i*16 + grp + half*8;
                float g = e1[(size_t)z*Sv + r]*0.125f;
                float rs = 0.f;
                #pragma unroll
                for (int j=0;j<4;j++){
                    int cn = col0 + warpN + j*8 + tig*2;
                    float s0 = c[i][j][half*2  ]*g + (1.f-mk[cn  ])*-10000.f;
                    float s1 = c[i][j][half*2+1]*g + (1.f-mk[cn+1])*-10000.f;
                    float2 o; o.x = __expf(s0); o.y = __expf(s1);
                    *(float2*)(Oz + (size_t)r*Sv + cn) = o;
                    rs += o.x + o.y;
                }
                rs += __shfl_xor_sync(0xffffffffu, rs, 1);
                rs += __shfl_xor_sync(0xffffffffu, rs, 2);
                if (tig==0) atomicAdd(&rowLp[r], rs);
            }
        }
    } else if (MODE==5){
        const int w = col0/Hv;                 // 0=Q 1=K 2=V (col block within one w)
        const float* bias = w==0?bias0 : w==1?bias1 : bias2;
        bf16* POh = w==0?Qh_ : (w==1?Kh_ : Vh_);
        bf16* POl = w==0?Ql_ : (w==1?Kl_ : Vl_);
        #pragma unroll
        for (int i=0;i<4;i++){
            #pragma unroll
            for (int j=0;j<4;j++){
                int cn  = col0 + warpN + j*8 + tig*2;
                int cl  = cn - w*Hv;
                int nh  = cl>>6, dh = cl&63;
                #pragma unroll
                for (int half=0; half<2; half++){
                    int r = row0 + warpM + i*16 + grp + half*8;
                    float x0 = c[i][j][half*2  ] + bias[cl  ];
                    float x1 = c[i][j][half*2+1] + bias[cl+1];
                    int b=r/Sv, s=r-b*Sv;
                    if (w<2){
                        size_t idx = (((size_t)(b*NHv+nh)*Sv+s)<<6)+dh;
                        __nv_bfloat162 h = __floats2bfloat162_rn(x0,x1);
                        __nv_bfloat162 l = __floats2bfloat162_rn(x0-__low2float(h), x1-__high2float(h));
                        *(__nv_bfloat162*)(POh+idx)=h;
                        *(__nv_bfloat162*)(POl+idx)=l;
                    } else {
                        size_t i0 = ((size_t)(b*NHv+nh)*DHv+dh)*Sv + s;
                        bf16 h0=__float2bfloat16(x0);
                        POh[i0]=h0; POl[i0]=__float2bfloat16(x0-__bfloat162float(h0));
                        bf16 h1=__float2bfloat16(x1);
                        POh[i0+Sv]=h1; POl[i0+Sv]=__float2bfloat16(x1-__bfloat162float(h1));
                    }
                }
            }
        }
    } else {   // MODE 4: Of = preln, e1 = residual (hs)
        #pragma unroll
        for (int i=0;i<4;i++){
            #pragma unroll
            for (int j=0;j<4;j++){
                int cn = col0 + warpN + j*8 + tig*2;
                #pragma unroll
                for (int half=0; half<2; half++){
                    int r = row0 + warpM + i*16 + grp + half*8;
                    size_t idx = (size_t)r*Hv + cn;
                    float2 o;
                    o.x = c[i][j][half*2  ] + bias0[cn  ] + e1[idx  ];
                    o.y = c[i][j][half*2+1] + bias0[cn+1] + e1[idx+1];
                    *(float2*)(Of+idx) = o;
                }
            }
        }
    }
}

// ---------------- PV: normalize (in smem) + probs write + ctx = P@V ----------
__global__ __launch_bounds__(256,2) void pv_kernel(
    float* __restrict__ probs,                 // in: unnormalized exp, out: probs
    const bf16* __restrict__ Vth, const bf16* __restrict__ Vtl,
    const float* __restrict__ rowL,
    bf16* __restrict__ ctxh, bf16* __restrict__ ctxl)
{
    constexpr int LDSK = 40;
    constexpr int LDSP = 36;
    constexpr int RAWST = 128*LDSP;            // fp32 elems per stage
    constexpr int VST   = 64*LDSK;             // bf16 elems per stage
    extern __shared__ char pvs[];
    float* raw = (float*)pvs;                               // 2*RAWST*4 = 36864B
    bf16* sPh  = (bf16*)(pvs + 36864);                      // 10240B
    bf16* sPl  = (bf16*)(pvs + 47104);                      // 10240B
    bf16* sVh  = (bf16*)(pvs + 57344);                      // 2 stages, 10240B
    bf16* sVl  = (bf16*)(pvs + 67584);                      // 10240B
    float* sI  = (float*)(pvs + 77824);                     // 512B

    const int tid = threadIdx.x, lane = tid & 31, warp = tid >> 5;
    const int grp = lane >> 2, tig = lane & 3;
    const int z = blockIdx.y, q0 = blockIdx.x*128;
    const int aRow  = lane & 15,        aCol8 = (lane >> 4) * 8;
    const int bRow  = (lane & 7) + ((lane >> 4) << 3);
    const int bCol8 = ((lane >> 3) & 1) * 8;

    if (tid < 128) sI[tid] = 1.f / rowL[(size_t)z*Sv + q0 + tid];

    const int warpM = (warp>>1)*32, warpN = (warp&1)*32;
    float c[2][4][4];
    #pragma unroll
    for (int i=0;i<2;i++)
        #pragma unroll
        for (int j=0;j<4;j++)
            #pragma unroll
            for (int r=0;r<4;r++) c[i][j][r]=0.f;

    float* Pz = probs + (size_t)z*Sv*Sv;
    const bf16* Vh_ = Vth + (size_t)z*DHv*Sv;
    const bf16* Vl_ = Vtl + (size_t)z*DHv*Sv;

    auto prefetch = [&](int kt, int st){
        const int k0 = kt*32;
        #pragma unroll
        for (int t=0;t<4;t++){
            int ch = tid + t*256;              // 1024 16B-chunks of raw P
            int r = ch>>3, q = ch&7;
            cpa16(&raw[st*RAWST + r*LDSP + q*4], &Pz[(size_t)(q0+r)*Sv + k0 + q*4]);
        }
        int r = tid>>2, cc = (tid&3)*8;
        cpa16(&sVh[st*VST + r*LDSK+cc], &Vh_[(size_t)r*Sv + k0 + cc]);
        cpa16(&sVl[st*VST + r*LDSK+cc], &Vl_[(size_t)r*Sv + k0 + cc]);
    };

    prefetch(0, 0); CP_COMMIT();
    const int cr = tid>>1, cc0 = (tid&1)*16;   // convert mapping: row, col base

    for (int kt=0; kt<Sv/32; kt++){
        const int st = kt & 1;
        __syncthreads();                       // prev mma done (sPh, V[st^1] free)
        if (kt+1 < Sv/32){ prefetch(kt+1, st^1); CP_COMMIT(); CP_WAIT1(); }
        else             { CP_WAIT0(); }
        __syncthreads();                       // stage st arrived for all
        {   // normalize raw -> probs gmem + bf16 split into sPh/sPl
            const int k0 = kt*32;
            float inv = sI[cr];
            #pragma unroll
            for (int c4=0;c4<4;c4++){
                float4 v = *(float4*)&raw[st*RAWST + cr*LDSP + cc0 + c4*4];
                float p0=v.x*inv, p1=v.y*inv, p2=v.z*inv, p3=v.w*inv;
                float4 pv_; pv_.x=p0; pv_.y=p1; pv_.z=p2; pv_.w=p3;
                *(float4*)&Pz[(size_t)(q0+cr)*Sv + k0 + cc0 + c4*4] = pv_;
                __nv_bfloat162 h01=__floats2bfloat162_rn(p0,p1), h23=__floats2bfloat162_rn(p2,p3);
                __nv_bfloat162 l01=__floats2bfloat162_rn(p0-__low2float(h01), p1-__high2float(h01));
                __nv_bfloat162 l23=__floats2bfloat162_rn(p2-__low2float(h23), p3-__high2float(h23));
                *(__nv_bfloat162*)&sPh[cr*LDSK + cc0 + c4*4    ]=h01;
                *(__nv_bfloat162*)&sPh[cr*LDSK + cc0 + c4*4 + 2]=h23;
                *(__nv_bfloat162*)&sPl[cr*LDSK + cc0 + c4*4    ]=l01;
                *(__nv_bfloat162*)&sPl[cr*LDSK + cc0 + c4*4 + 2]=l23;
            }
        }
        __syncthreads();                       // sPh/sPl ready
        const bf16* pVh = sVh + st*VST;
        const bf16* pVl = sVl + st*VST;
        #pragma unroll
        for (int ks=0;ks<32;ks+=16){
            u32 a[2][4], b_h[4][2], b_l[4][2];
            #pragma unroll
            for (int jj=0; jj<4; jj+=2){
                ldm_x4(b_h[jj][0], b_h[jj][1], b_h[jj+1][0], b_h[jj+1][1],
                       &pVh[(warpN + jj*8 + bRow)*LDSK + ks + bCol8]);
                ldm_x4(b_l[jj][0], b_l[jj][1], b_l[jj+1][0], b_l[jj+1][1],
                       &pVl[(warpN + jj*8 + bRow)*LDSK + ks + bCol8]);
            }
            #pragma unroll
            for (int i=0;i<2;i++)
                ldm_x4(a[i][0],a[i][1],a[i][2],a[i][3],
                       &sPh[(warpM + i*16 + aRow)*LDSK + ks + aCol8]);
            #pragma unroll
            for (int i=0;i<2;i++)
                #pragma unroll
                for (int j=0;j<4;j++){
                    mma16816(c[i][j][0],c[i][j][1],c[i][j][2],c[i][j][3], a[i], b_h[j]);
                    mma16816(c[i][j][0],c[i][j][1],c[i][j][2],c[i][j][3], a[i], b_l[j]);
                }
            #pragma unroll
            for (int i=0;i<2;i++)
                ldm_x4(a[i][0],a[i][1],a[i][2],a[i][3],
                       &sPl[(warpM + i*16 + aRow)*LDSK + ks + aCol8]);
            #pragma unroll
            for (int i=0;i<2;i++)
                #pragma unroll
                for (int j=0;j<4;j++)
                    mma16816(c[i][j][0],c[i][j][1],c[i][j][2],c[i][j][3], a[i], b_h[j]);
        }
    }

    const int b = z/NHv, nh = z%NHv;
    #pragma unroll
    for (int i=0;i<2;i++){
        #pragma unroll
        for (int j=0;j<4;j++){
            int dh = warpN + j*8 + tig*2;
            #pragma unroll
            for (int half=0; half<2; half++){
                int s = q0 + warpM + i*16 + grp + half*8;
                float x0 = c[i][j][half*2], x1 = c[i][j][half*2+1];
                size_t idx = ((size_t)b*Sv + s)*Hv + nh*DHv + dh;
                __nv_bfloat162 h = __floats2bfloat162_rn(x0,x1);
                __nv_bfloat162 l = __floats2bfloat162_rn(x0-__low2float(h), x1-__high2float(h));
                *(__nv_bfloat162*)(ctxh+idx)=h;
                *(__nv_bfloat162*)(ctxl+idx)=l;
            }
        }
    }
}

// ---------------- helpers ----------------------------------------------------
__device__ __forceinline__ float blockReduceSum(float v, float* red){
    #pragma unroll
    for (int o=16;o;o>>=1) v += __shfl_xor_sync(0xffffffffu, v, o);
    const int lane = threadIdx.x & 31, wid = threadIdx.x >> 5;
    const int nw = blockDim.x >> 5;
    __syncthreads();
    if (lane==0) red[wid]=v;
    __syncthreads();
    if (threadIdx.x==0){
        float s=0.f;
        for (int i=0;i<nw;i++) s+=red[i];
        red[32]=s;
    }
    __syncthreads();
    return red[32];
}

// ---------------- wormhole gate ----------------------------------------------
__global__ __launch_bounds__(128) void gate_kernel(
    const float* __restrict__ hs, const float* __restrict__ Wg1, const float* __restrict__ bg1,
    const float* __restrict__ glnw, const float* __restrict__ glnb,
    const float* __restrict__ Wg2, const float* __restrict__ bg2,
    float* __restrict__ gates)
{
    const int ROWS=8;
    __shared__ float hs_s[ROWS*Hv];
    __shared__ float g_s[ROWS][WHv+4];
    __shared__ float red[40];
    const int tid = threadIdx.x;
    const size_t rowbase = (size_t)blockIdx.x*ROWS;

    for (int i=tid;i<ROWS*Hv;i+=128) hs_s[i] = hs[rowbase*Hv + i];
    __syncthreads();

    float acc[ROWS];
    #pragma unroll
    for (int r=0;r<ROWS;r++) acc[r]=bg1[tid];
    for (int h=0;h<Hv;h++){
        float wv = Wg1[h*WHv + tid];
        #pragma unroll
        for (int r=0;r<ROWS;r++) acc[r] = fmaf(hs_s[r*Hv+h], wv, acc[r]);
    }
    float lw = glnw[tid], lb = glnb[tid];
    #pragma unroll
    for (int r=0;r<ROWS;r++){
        float mu  = blockReduceSum(acc[r], red) * (1.f/WHv);
        float d   = acc[r]-mu;
        float var = blockReduceSum(d*d, red) * (1.f/WHv);
        float gv  = d*rsqrtf(var+1e-12f)*lw + lb;
        g_s[r][tid] = fmaxf(gv, 0.f);
    }
    __syncthreads();
    if (tid < ROWS*NHv){
        int r = tid/NHv, o = tid%NHv;
        float s = bg2[o];
        for (int c=0;c<WHv;c++) s = fmaf(g_s[r][c], Wg2[c*NHv+o], s);
        float gate = 1.f/(1.f+__expf(-s));
        size_t row = rowbase + r;
        int b = (int)(row/Sv), sq = (int)(row%Sv);
        gates[((size_t)(b*NHv+o))*Sv + sq] = gate;
    }
}

// ---------------- final residual LayerNorm -----------------------------------
__global__ __launch_bounds__(256) void ln_kernel(const float* __restrict__ x,
    const float* __restrict__ w, const float* __restrict__ b, float* __restrict__ out)
{
    __shared__ float xs[Hv];
    __shared__ float red[40];
    const size_t row = blockIdx.x;
    const float* xr = x + row*Hv;
    float partial = 0.f;
    for (int i=threadIdx.x;i<Hv;i+=256){ float v=xr[i]; xs[i]=v; partial+=v; }
    float mu = blockReduceSum(partial, red)*(1.f/Hv);
    float p2=0.f;
    for (int i=threadIdx.x;i<Hv;i+=256){ float d=xs[i]-mu; p2+=d*d; }
    float var = blockReduceSum(p2, red)*(1.f/Hv);
    float rs = rsqrtf(var+1e-12f);
    float* o = out + row*Hv;
    for (int i=threadIdx.x;i<Hv;i+=256) o[i] = (xs[i]-mu)*rs*w[i] + b[i];
}

// ---------------- launcher ----------------------------------------------------
extern "C" void kernel_launch(void* const* d_in, const int* in_sizes, int n_in,
                              void* d_out, int out_size)
{
    const float* hs  =(const float*)d_in[0];
    const float* am  =(const float*)d_in[1];
    const float* Wq  =(const float*)d_in[2];
    const float* bq  =(const float*)d_in[3];
    const float* Wk  =(const float*)d_in[4];
    const float* bk  =(const float*)d_in[5];
    const float* Wv  =(const float*)d_in[6];
    const float* bvb =(const float*)d_in[7];
    const float* Wg1 =(const float*)d_in[8];
    const float* bg1 =(const float*)d_in[9];
    const float* glnw=(const float*)d_in[10];
    const float* glnb=(const float*)d_in[11];
    const float* Wg2 =(const float*)d_in[12];
    const float* bg2 =(const float*)d_in[13];
    const float* Wo  =(const float*)d_in[14];
    const float* bo  =(const float*)d_in[15];
    const float* lnw =(const float*)d_in[16];
    const float* lnb =(const float*)d_in[17];

    float* out   = (float*)d_out;
    float* probs = out + (size_t)Bv*Sv*Hv;   // tuple order: (out, probs)

    bf16 *hsh,*hsl,*Wth,*Wtl,*Qh,*Ql,*Kh,*Kl,*Vth,*Vtl,*ctxh,*ctxl;
    float *preln,*gates,*rowL;
    cudaGetSymbolAddress((void**)&hsh,  g_hsh);
    cudaGetSymbolAddress((void**)&hsl,  g_hsl);
    cudaGetSymbolAddress((void**)&Wth,  g_Wth);
    cudaGetSymbolAddress((void**)&Wtl,  g_Wtl);
    cudaGetSymbolAddress((void**)&Qh,   g_Qh);
    cudaGetSymbolAddress((void**)&Ql,   g_Ql);
    cudaGetSymbolAddress((void**)&Kh,   g_Kh);
    cudaGetSymbolAddress((void**)&Kl,   g_Kl);
    cudaGetSymbolAddress((void**)&Vth,  g_Vth);
    cudaGetSymbolAddress((void**)&Vtl,  g_Vtl);
    cudaGetSymbolAddress((void**)&ctxh, g_ctxh);
    cudaGetSymbolAddress((void**)&ctxl, g_ctxl);
    cudaGetSymbolAddress((void**)&preln,g_preln);
    cudaGetSymbolAddress((void**)&gates,g_gates);
    cudaGetSymbolAddress((void**)&rowL, g_rowL);

    const int M = Bv*Sv;
    const int SMEM_GEMM = 2*4*128*40*(int)sizeof(bf16);   // 81920 B
    const int SMEM_PV   = 78400;

    cudaFuncSetAttribute(mmagemm<3>, cudaFuncAttributeMaxDynamicSharedMemorySize, SMEM_GEMM);
    cudaFuncSetAttribute(mmagemm<4>, cudaFuncAttributeMaxDynamicSharedMemorySize, SMEM_GEMM);
    cudaFuncSetAttribute(mmagemm<5>, cudaFuncAttributeMaxDynamicSharedMemorySize, SMEM_GEMM);
    cudaFuncSetAttribute(pv_kernel,  cudaFuncAttributeMaxDynamicSharedMemorySize, SMEM_PV);

    // prep: zero rowL, input split, weight transpose+split, gates
    cudaMemsetAsync(rowL, 0, (size_t)Bv*NHv*Sv*sizeof(float));
    int n4 = M*Hv/4;
    split_kernel<<<(n4+255)/256, 256>>>(hs, hsh, hsl, n4);
    wsplit_kernel<<<dim3(24,24,4), 256>>>(Wq, Wk, Wv, Wo);
    gate_kernel<<<M/8, 128>>>(hs, Wg1, bg1, glnw, glnb, Wg2, bg2, gates);

    // fused QKV projection (N = 3H against stacked W^T)
    dim3 gQKV(3*Hv/128, M/128, 1);
    mmagemm<5><<<gQKV,256,SMEM_GEMM>>>(hsh,hsl,Hv,0, Wth,Wtl,Hv,0,
        bq, bk, bvb, nullptr, nullptr,
        Qh,Ql, Kh,Kl, Vth,Vtl, nullptr, nullptr, Hv);

    // scores -> exp(gate*qk/8 + mask) unnormalized into probs region + rowL sums
    dim3 gScore(Sv/128, Sv/128, Bv*NHv);
    mmagemm<3><<<gScore,256,SMEM_GEMM>>>(Qh,Ql,DHv,(size_t)Sv*DHv, Kh,Kl,DHv,(size_t)Sv*DHv,
        nullptr,nullptr,nullptr, gates, am,
        nullptr,nullptr,nullptr,nullptr,nullptr,nullptr, probs, rowL, DHv);

    // PV: normalize + probs write + ctx (bf16 split)
    pv_kernel<<<dim3(Sv/128, Bv*NHv), 256, SMEM_PV>>>(probs, Vth, Vtl, rowL, ctxh, ctxl);

    // out projection + bias + residual, then LayerNorm  (e1 = hs residual, Of = preln)
    dim3 gWo(Hv/128, M/128, 1);
    mmagemm<4><<<gWo,256,SMEM_GEMM>>>(ctxh,ctxl,Hv,0, Wth+(size_t)3*Hv*Hv,Wtl+(size_t)3*Hv*Hv,Hv,0,
        bo, nullptr, nullptr, hs, nullptr,
        nullptr,nullptr,nullptr,nullptr,nullptr,nullptr, preln, nullptr, Hv);
    ln_kernel<<<M,256>>>(preln, lnw, lnb, out);
}